// round 8
// baseline (speedup 1.0000x reference)
#include <cuda_runtime.h>
#include <cuda_bf16.h>
#include <math.h>
#include <stdint.h>

// ---------------- problem constants ----------------
#define BATCH 4
#define SEQ   2048
#define CEMB  1024
#define NHEAD 16
#define HDIM  64
#define ROWS  (BATCH*SEQ)        // 8192
#define C3    (3*CEMB)           // 3072
#define C4    (4*CEMB)           // 4096

// ---------------- scratch (no cudaMalloc allowed) ----------------
__device__ float g_x2 [(size_t)ROWS*CEMB];
__device__ __nv_bfloat16 g_qkvh[(size_t)ROWS*C3], g_qkvl[(size_t)ROWS*C3];
__device__ __nv_bfloat16 g_a_hi[(size_t)ROWS*CEMB], g_a_lo[(size_t)ROWS*CEMB];
__device__ __nv_bfloat16 g_y_hi[(size_t)ROWS*CEMB], g_y_lo[(size_t)ROWS*CEMB];
__device__ __nv_bfloat16 g_h_hi[(size_t)ROWS*C4],  g_h_lo[(size_t)ROWS*C4];
__device__ __nv_bfloat16 g_wq_hi[(size_t)C3*CEMB],  g_wq_lo[(size_t)C3*CEMB];
__device__ __nv_bfloat16 g_wp_hi[(size_t)CEMB*CEMB],g_wp_lo[(size_t)CEMB*CEMB];
__device__ __nv_bfloat16 g_wf_hi[(size_t)C4*CEMB],  g_wf_lo[(size_t)C4*CEMB];
__device__ __nv_bfloat16 g_w2_hi[(size_t)CEMB*C4],  g_w2_lo[(size_t)CEMB*C4];

// ---------------- PTX helpers (family-safe: cp.async / ldmatrix / mma.sync) ----------------
__device__ __forceinline__ uint32_t s2u(const void* p) {
    uint32_t a;
    asm("{ .reg .u64 t; cvta.to.shared.u64 t, %1; cvt.u32.u64 %0, t; }" : "=r"(a) : "l"(p));
    return a;
}
__device__ __forceinline__ uint32_t swz(uint32_t o) { return o ^ ((o >> 3) & 0x70); }

__device__ __forceinline__ void cp16(uint32_t s, const void* g) {
    asm volatile("cp.async.cg.shared.global [%0], [%1], 16;" :: "r"(s), "l"(g));
}
__device__ __forceinline__ void cp_commit() { asm volatile("cp.async.commit_group;"); }
#define CP_WAIT(N) asm volatile("cp.async.wait_group %0;" :: "n"(N))

__device__ __forceinline__ void ldsm4(uint32_t* r, uint32_t addr) {
    asm volatile("ldmatrix.sync.aligned.m8n8.x4.shared.b16 {%0,%1,%2,%3}, [%4];"
                 : "=r"(r[0]), "=r"(r[1]), "=r"(r[2]), "=r"(r[3]) : "r"(addr));
}
__device__ __forceinline__ void ldsm2(uint32_t* r, uint32_t addr) {
    asm volatile("ldmatrix.sync.aligned.m8n8.x2.shared.b16 {%0,%1}, [%2];"
                 : "=r"(r[0]), "=r"(r[1]) : "r"(addr));
}
__device__ __forceinline__ void ldsm2t(uint32_t* r, uint32_t addr) {
    asm volatile("ldmatrix.sync.aligned.m8n8.x2.trans.shared.b16 {%0,%1}, [%2];"
                 : "=r"(r[0]), "=r"(r[1]) : "r"(addr));
}
__device__ __forceinline__ void mma16816(float* c, const uint32_t* a, const uint32_t* b) {
    asm volatile("mma.sync.aligned.m16n8k16.row.col.f32.bf16.bf16.f32 "
                 "{%0,%1,%2,%3}, {%4,%5,%6,%7}, {%8,%9}, {%0,%1,%2,%3};"
                 : "+f"(c[0]), "+f"(c[1]), "+f"(c[2]), "+f"(c[3])
                 : "r"(a[0]), "r"(a[1]), "r"(a[2]), "r"(a[3]), "r"(b[0]), "r"(b[1]));
}

// ---------------- split helpers ----------------
__device__ __forceinline__ void store_split4(__nv_bfloat16* hip, __nv_bfloat16* lop,
                                             size_t off, float v0, float v1, float v2, float v3) {
    __nv_bfloat162 h0 = __floats2bfloat162_rn(v0, v1);
    __nv_bfloat162 h1 = __floats2bfloat162_rn(v2, v3);
    float l0 = v0 - __low2float(h0),  l1 = v1 - __high2float(h0);
    float l2 = v2 - __low2float(h1),  l3 = v3 - __high2float(h1);
    *reinterpret_cast<__nv_bfloat162*>(hip + off)     = h0;
    *reinterpret_cast<__nv_bfloat162*>(hip + off + 2) = h1;
    *reinterpret_cast<__nv_bfloat162*>(lop + off)     = __floats2bfloat162_rn(l0, l1);
    *reinterpret_cast<__nv_bfloat162*>(lop + off + 2) = __floats2bfloat162_rn(l2, l3);
}
__device__ __forceinline__ void store_split2(__nv_bfloat16* hip, __nv_bfloat16* lop,
                                             size_t off, float v0, float v1) {
    __nv_bfloat162 h = __floats2bfloat162_rn(v0, v1);
    float l0 = v0 - __low2float(h), l1 = v1 - __high2float(h);
    *reinterpret_cast<__nv_bfloat162*>(hip + off) = h;
    *reinterpret_cast<__nv_bfloat162*>(lop + off) = __floats2bfloat162_rn(l0, l1);
}

// ---------------- layernorm -> bf16 hi/lo split ----------------
__global__ void ln_split_kernel(const float* __restrict__ x, const float* __restrict__ g,
                                const float* __restrict__ b,
                                __nv_bfloat16* __restrict__ ohi, __nv_bfloat16* __restrict__ olo) {
    int row = blockIdx.x;
    int tid = threadIdx.x;
    const float4 v = ((const float4*)(x + (size_t)row * CEMB))[tid];
    float s  = v.x + v.y + v.z + v.w;
    float sq = v.x * v.x + v.y * v.y + v.z * v.z + v.w * v.w;
    #pragma unroll
    for (int o = 16; o; o >>= 1) {
        s  += __shfl_xor_sync(0xffffffffu, s,  o);
        sq += __shfl_xor_sync(0xffffffffu, sq, o);
    }
    __shared__ float ss[8], sqs[8];
    if ((tid & 31) == 0) { ss[tid >> 5] = s; sqs[tid >> 5] = sq; }
    __syncthreads();
    float tot = 0.f, totq = 0.f;
    #pragma unroll
    for (int w = 0; w < 8; ++w) { tot += ss[w]; totq += sqs[w]; }
    const float mu   = tot * (1.f / CEMB);
    const float var  = totq * (1.f / CEMB) - mu * mu;
    const float rstd = rsqrtf(var + 1e-5f);
    const float4 gg = ((const float4*)g)[tid];
    const float4 bb = ((const float4*)b)[tid];
    float r0 = (v.x - mu) * rstd * gg.x + bb.x;
    float r1 = (v.y - mu) * rstd * gg.y + bb.y;
    float r2 = (v.z - mu) * rstd * gg.z + bb.z;
    float r3 = (v.w - mu) * rstd * gg.w + bb.w;
    store_split4(ohi, olo, (size_t)row * CEMB + tid * 4, r0, r1, r2, r3);
}

// ---------------- weight transpose + split ----------------
__global__ void wt_kernel(const float* __restrict__ w, __nv_bfloat16* __restrict__ whi,
                          __nv_bfloat16* __restrict__ wlo, int K, int N) {
    __shared__ float t[32][33];
    int n0 = blockIdx.x * 32, k0 = blockIdx.y * 32;
    int tx = threadIdx.x, ty = threadIdx.y;
    #pragma unroll
    for (int i = 0; i < 4; ++i)
        t[ty + 8 * i][tx] = w[(size_t)(k0 + ty + 8 * i) * N + n0 + tx];
    __syncthreads();
    #pragma unroll
    for (int i = 0; i < 4; ++i) {
        int r = ty + 8 * i;
        float v = t[tx][r];
        __nv_bfloat16 h = __float2bfloat16(v);
        whi[(size_t)(n0 + r) * K + k0 + tx] = h;
        wlo[(size_t)(n0 + r) * K + k0 + tx] = __float2bfloat16(v - __bfloat162float(h));
    }
}

__device__ __forceinline__ float gelu_t(float v) {
    float u = 0.7978845608028654f * (v + 0.044715f * v * v * v);
    return 0.5f * v * (1.f + tanhf(u));
}

// ---------------- HMMA GEMM; EPI: 1=bias+gelu->split, 2=bias+res->f32, 3=bias->split ----------------
#define TILE_M 128
#define TILE_N 128
#define KCH    64
#define STAGES 4
#define STG_BYTES (TILE_M * 128 + TILE_N * 128)
#define GSMEM (STAGES * STG_BYTES)

template<int EPI>
__global__ __launch_bounds__(256) void hmma_gemm(
    const __nv_bfloat16* __restrict__ Ahi, const __nv_bfloat16* __restrict__ Alo,
    const __nv_bfloat16* __restrict__ Bhi, const __nv_bfloat16* __restrict__ Blo,
    const float* __restrict__ bias, const float* __restrict__ res,
    float* __restrict__ Cf, __nv_bfloat16* __restrict__ Chi, __nv_bfloat16* __restrict__ Clo,
    int M, int N, int K)
{
    extern __shared__ char smem[];
    const uint32_t sb = s2u(smem);
    const int tid = threadIdx.x, wid = tid >> 5, lane = tid & 31;
    const int wm = wid & 1, wn = wid >> 1;
    const int row0 = blockIdx.y * TILE_M, col0 = blockIdx.x * TILE_N;
    const int cpt = K / KCH, NKC = 3 * cpt;

    auto load_chunk = [&](int kc) {
        int s = kc % STAGES;
        int t = kc / cpt;
        int k0 = (kc - t * cpt) * KCH;
        const __nv_bfloat16* A = (t < 2) ? Ahi : Alo;
        const __nv_bfloat16* B = (t == 1) ? Blo : Bhi;
        uint32_t sA = sb + s * STG_BYTES;
        uint32_t sB = sA + TILE_M * 128;
        #pragma unroll
        for (int i = 0; i < 4; ++i) {
            int idx = i * 256 + tid;
            int r = idx >> 3, c = (idx & 7) * 16;
            cp16(sA + swz(r * 128 + c), A + (size_t)(row0 + r) * K + k0 + (c >> 1));
        }
        #pragma unroll
        for (int i = 0; i < 4; ++i) {
            int idx = i * 256 + tid;
            int r = idx >> 3, c = (idx & 7) * 16;
            cp16(sB + swz(r * 128 + c), B + (size_t)(col0 + r) * K + k0 + (c >> 1));
        }
        cp_commit();
    };

    float acc[4][4][4];
    #pragma unroll
    for (int mt = 0; mt < 4; ++mt)
        #pragma unroll
        for (int nt = 0; nt < 4; ++nt)
            #pragma unroll
            for (int q = 0; q < 4; ++q) acc[mt][nt][q] = 0.f;

    for (int kc = 0; kc < STAGES - 1; ++kc) load_chunk(kc);

    const int arow = (lane & 7) + ((lane >> 3) & 1) * 8;
    const int akof = ((lane >> 4) & 1) * 8;
    const int brow = lane & 7;
    const int bkof = ((lane >> 3) & 1) * 8;

    for (int kc = 0; kc < NKC; ++kc) {
        int s = kc % STAGES;
        CP_WAIT(STAGES - 2);
        __syncthreads();
        if (kc + STAGES - 1 < NKC) load_chunk(kc + STAGES - 1);
        else cp_commit();
        uint32_t sA = sb + s * STG_BYTES;
        uint32_t sB = sA + TILE_M * 128;
        #pragma unroll
        for (int ks = 0; ks < KCH / 16; ++ks) {
            uint32_t a[4][4], b[4][2];
            #pragma unroll
            for (int mt = 0; mt < 4; ++mt) {
                uint32_t o = (uint32_t)(wm * 64 + mt * 16 + arow) * 128 + (ks * 16 + akof) * 2;
                ldsm4(a[mt], sA + swz(o));
            }
            #pragma unroll
            for (int nt = 0; nt < 4; ++nt) {
                uint32_t o = (uint32_t)(wn * 32 + nt * 8 + brow) * 128 + (ks * 16 + bkof) * 2;
                ldsm2(b[nt], sB + swz(o));
            }
            #pragma unroll
            for (int mt = 0; mt < 4; ++mt)
                #pragma unroll
                for (int nt = 0; nt < 4; ++nt)
                    mma16816(acc[mt][nt], a[mt], b[nt]);
        }
    }

    const int g = lane >> 2, i2 = (lane & 3) * 2;
    #pragma unroll
    for (int mt = 0; mt < 4; ++mt) {
        #pragma unroll
        for (int nt = 0; nt < 4; ++nt) {
            int r = row0 + wm * 64 + mt * 16 + g;
            int c = col0 + wn * 32 + nt * 8 + i2;
            float2 bv = *(const float2*)(bias + c);
            #pragma unroll
            for (int half = 0; half < 2; ++half) {
                int rr = r + half * 8;
                float v0 = acc[mt][nt][half * 2 + 0] + bv.x;
                float v1 = acc[mt][nt][half * 2 + 1] + bv.y;
                if (EPI == 1) {
                    v0 = gelu_t(v0); v1 = gelu_t(v1);
                    store_split2(Chi, Clo, (size_t)rr * N + c, v0, v1);
                } else if (EPI == 3) {
                    store_split2(Chi, Clo, (size_t)rr * N + c, v0, v1);
                } else {
                    if (EPI == 2) {
                        float2 rv = *(const float2*)(res + (size_t)rr * N + c);
                        v0 += rv.x; v1 += rv.y;
                    }
                    float2 ov; ov.x = v0; ov.y = v1;
                    *(float2*)(Cf + (size_t)rr * N + c) = ov;
                }
            }
        }
    }
}

// ---------------- HMMA flash attention: Q tile 128, K tile 64, split both matmuls ----------------
#define AQT 128
#define AKT 64
#define ASMEM (32768 + 2 * 32768)   // 98304

__global__ __launch_bounds__(256, 2) void attn_hmma(
    const __nv_bfloat16* __restrict__ qkvh, const __nv_bfloat16* __restrict__ qkvl,
    __nv_bfloat16* __restrict__ yhi, __nv_bfloat16* __restrict__ ylo)
{
    extern __shared__ char smem[];
    const uint32_t sb = s2u(smem);
    const int tid = threadIdx.x, wid = tid >> 5, lane = tid & 31;
    const int qb = blockIdx.x, bh = blockIdx.y;
    const int b = bh >> 4, h = bh & 15;
    const int q0 = qb * AQT;
    const size_t rowbase = (size_t)b * SEQ;
    const size_t qcol = (size_t)h * HDIM, kcol = CEMB + qcol, vcol = 2 * CEMB + qcol;

    const uint32_t sPh = sb, sPl = sb + 16384;

    // load Q (hi/lo) : group G0
    #pragma unroll
    for (int i = 0; i < 4; ++i) {
        int idx = i * 256 + tid;
        int r = idx >> 3, c = (idx & 7) * 16;
        size_t grow = (rowbase + q0 + r) * C3 + qcol + (c >> 1);
        cp16(sPh + swz(r * 128 + c), qkvh + grow);
        cp16(sPl + swz(r * 128 + c), qkvl + grow);
    }
    cp_commit();

    auto load_kv = [&](int kt, int s) {
        uint32_t base = sb + 32768 + s * 32768;
        #pragma unroll
        for (int i = 0; i < 2; ++i) {
            int idx = i * 256 + tid;
            int r = idx >> 3, c = (idx & 7) * 16;
            size_t grow = (rowbase + kt * AKT + r) * C3;
            uint32_t so = swz(r * 128 + c);
            cp16(base + so,         qkvh + grow + kcol + (c >> 1));
            cp16(base + 8192 + so,  qkvl + grow + kcol + (c >> 1));
            cp16(base + 16384 + so, qkvh + grow + vcol + (c >> 1));
            cp16(base + 24576 + so, qkvl + grow + vcol + (c >> 1));
        }
        cp_commit();
    };
    load_kv(0, 0);                       // G1

    const int nkt = 2 * qb + 2;

    CP_WAIT(1);                          // G0 (Q) done
    __syncthreads();
    const int frow = (lane & 7) + ((lane >> 3) & 1) * 8;
    const int fkof = ((lane >> 4) & 1) * 8;
    uint32_t qh[4][4], ql[4][4];
    #pragma unroll
    for (int ks = 0; ks < 4; ++ks) {
        uint32_t o = (uint32_t)(wid * 16 + frow) * 128 + (ks * 16 + fkof) * 2;
        ldsm4(qh[ks], sPh + swz(o));
        ldsm4(ql[ks], sPl + swz(o));
    }
    __syncthreads();                     // Q region becomes P region

    float m0 = -1e30f, m1 = -1e30f, l0 = 0.f, l1 = 0.f;
    float o_[8][4];
    #pragma unroll
    for (int nt = 0; nt < 8; ++nt)
        #pragma unroll
        for (int q = 0; q < 4; ++q) o_[nt][q] = 0.f;

    const int g = lane >> 2;
    const int qr0 = q0 + wid * 16 + g;
    const int ccol = (lane & 3) * 2;

    for (int kt = 0; kt < nkt; ++kt) {
        int s = kt & 1;
        if (kt + 1 < nkt) load_kv(kt + 1, s ^ 1); else cp_commit();
        CP_WAIT(1);
        __syncthreads();
        uint32_t Kh = sb + 32768 + s * 32768;
        uint32_t Kl = Kh + 8192, Vh = Kh + 16384, Vl = Kh + 24576;

        // S = Q K^T (3-term split)
        float sa[8][4];
        #pragma unroll
        for (int nt = 0; nt < 8; ++nt) {
            sa[nt][0] = sa[nt][1] = sa[nt][2] = sa[nt][3] = 0.f;
            #pragma unroll
            for (int ks = 0; ks < 4; ++ks) {
                uint32_t bo = (uint32_t)(nt * 8 + (lane & 7)) * 128 +
                              (ks * 16 + ((lane >> 3) & 1) * 8) * 2;
                uint32_t kh2[2], kl2[2];
                ldsm2(kh2, Kh + swz(bo));
                ldsm2(kl2, Kl + swz(bo));
                mma16816(sa[nt], qh[ks], kh2);
                mma16816(sa[nt], qh[ks], kl2);
                mma16816(sa[nt], ql[ks], kh2);
            }
        }

        // scale + causal mask
        const int k0g = kt * AKT;
        const bool tmask = (k0g + AKT - 1) > qr0;
        #pragma unroll
        for (int nt = 0; nt < 8; ++nt) {
            int c0g = k0g + nt * 8 + ccol;
            #pragma unroll
            for (int q = 0; q < 4; ++q) sa[nt][q] *= 0.125f;
            if (tmask) {
                if (c0g > qr0)         sa[nt][0] = -1e30f;
                if (c0g + 1 > qr0)     sa[nt][1] = -1e30f;
                if (c0g > qr0 + 8)     sa[nt][2] = -1e30f;
                if (c0g + 1 > qr0 + 8) sa[nt][3] = -1e30f;
            }
        }

        // online softmax
        float mt0 = -1e30f, mt1 = -1e30f;
        #pragma unroll
        for (int nt = 0; nt < 8; ++nt) {
            mt0 = fmaxf(mt0, fmaxf(sa[nt][0], sa[nt][1]));
            mt1 = fmaxf(mt1, fmaxf(sa[nt][2], sa[nt][3]));
        }
        mt0 = fmaxf(mt0, __shfl_xor_sync(0xffffffffu, mt0, 1));
        mt0 = fmaxf(mt0, __shfl_xor_sync(0xffffffffu, mt0, 2));
        mt1 = fmaxf(mt1, __shfl_xor_sync(0xffffffffu, mt1, 1));
        mt1 = fmaxf(mt1, __shfl_xor_sync(0xffffffffu, mt1, 2));
        float mn0 = fmaxf(m0, mt0), mn1 = fmaxf(m1, mt1);
        float a0 = __expf(m0 - mn0), a1 = __expf(m1 - mn1);
        m0 = mn0; m1 = mn1;
        float rs0 = 0.f, rs1 = 0.f;
        #pragma unroll
        for (int nt = 0; nt < 8; ++nt) {
            sa[nt][0] = __expf(sa[nt][0] - mn0);
            sa[nt][1] = __expf(sa[nt][1] - mn0);
            sa[nt][2] = __expf(sa[nt][2] - mn1);
            sa[nt][3] = __expf(sa[nt][3] - mn1);
            rs0 += sa[nt][0] + sa[nt][1];
            rs1 += sa[nt][2] + sa[nt][3];
        }
        rs0 += __shfl_xor_sync(0xffffffffu, rs0, 1);
        rs0 += __shfl_xor_sync(0xffffffffu, rs0, 2);
        rs1 += __shfl_xor_sync(0xffffffffu, rs1, 1);
        rs1 += __shfl_xor_sync(0xffffffffu, rs1, 2);
        l0 = l0 * a0 + rs0;
        l1 = l1 * a1 + rs1;
        #pragma unroll
        for (int nt = 0; nt < 8; ++nt) {
            o_[nt][0] *= a0; o_[nt][1] *= a0;
            o_[nt][2] *= a1; o_[nt][3] *= a1;
        }

        // store P (hi/lo) to smem (warp-private rows, swizzle conflict-free)
        #pragma unroll
        for (int nt = 0; nt < 8; ++nt) {
            int cb = nt * 16 + (lane & 3) * 4;
            #pragma unroll
            for (int half = 0; half < 2; ++half) {
                float p0 = sa[nt][half * 2 + 0], p1 = sa[nt][half * 2 + 1];
                __nv_bfloat162 hv = __floats2bfloat162_rn(p0, p1);
                float r0f = p0 - __low2float(hv), r1f = p1 - __high2float(hv);
                __nv_bfloat162 lv = __floats2bfloat162_rn(r0f, r1f);
                uint32_t off = swz((uint32_t)(wid * 16 + g + half * 8) * 128 + cb);
                *reinterpret_cast<__nv_bfloat162*>(smem + off)         = hv;
                *reinterpret_cast<__nv_bfloat162*>(smem + 16384 + off) = lv;
            }
        }
        __syncwarp();

        // O += P V (3-term split), V via ldmatrix.trans
        #pragma unroll
        for (int ks = 0; ks < 4; ++ks) {
            uint32_t ao = (uint32_t)(wid * 16 + frow) * 128 + (ks * 16 + fkof) * 2;
            uint32_t ph[4], pl[4];
            ldsm4(ph, sPh + swz(ao));
            ldsm4(pl, sPl + swz(ao));
            #pragma unroll
            for (int nt = 0; nt < 8; ++nt) {
                uint32_t vo = (uint32_t)(ks * 16 + (lane & 15)) * 128 + nt * 16;
                uint32_t vh2[2], vl2[2];
                ldsm2t(vh2, Vh + swz(vo));
                ldsm2t(vl2, Vl + swz(vo));
                mma16816(o_[nt], ph, vh2);
                mma16816(o_[nt], ph, vl2);
                mma16816(o_[nt], pl, vh2);
            }
        }
        __syncthreads();
    }

    float i0 = 1.f / l0, i1 = 1.f / l1;
    #pragma unroll
    for (int nt = 0; nt < 8; ++nt) {
        size_t col = qcol + nt * 8 + ccol;
        store_split2(yhi, ylo, (rowbase + qr0) * CEMB + col,     o_[nt][0] * i0, o_[nt][1] * i0);
        store_split2(yhi, ylo, (rowbase + qr0 + 8) * CEMB + col, o_[nt][2] * i1, o_[nt][3] * i1);
    }
}

// ---------------- launch ----------------
extern "C" void kernel_launch(void* const* d_in, const int* in_sizes, int n_in,
                              void* d_out, int out_size) {
    const float* x      = (const float*)d_in[0];
    const float* ln1_g  = (const float*)d_in[1];
    const float* ln1_b  = (const float*)d_in[2];
    const float* w_attn = (const float*)d_in[3];
    const float* b_attn = (const float*)d_in[4];
    const float* w_proj = (const float*)d_in[5];
    const float* b_proj = (const float*)d_in[6];
    const float* ln2_g  = (const float*)d_in[7];
    const float* ln2_b  = (const float*)d_in[8];
    const float* w_fc   = (const float*)d_in[9];
    const float* b_fc   = (const float*)d_in[10];
    const float* w_fc2  = (const float*)d_in[11];
    const float* b_fc2  = (const float*)d_in[12];
    float* out = (float*)d_out;

    void* p;
    cudaGetSymbolAddress(&p, g_x2);   float* x2  = (float*)p;
    cudaGetSymbolAddress(&p, g_qkvh); __nv_bfloat16* qvh = (__nv_bfloat16*)p;
    cudaGetSymbolAddress(&p, g_qkvl); __nv_bfloat16* qvl = (__nv_bfloat16*)p;
    cudaGetSymbolAddress(&p, g_a_hi); __nv_bfloat16* ahi = (__nv_bfloat16*)p;
    cudaGetSymbolAddress(&p, g_a_lo); __nv_bfloat16* alo = (__nv_bfloat16*)p;
    cudaGetSymbolAddress(&p, g_y_hi); __nv_bfloat16* yhi = (__nv_bfloat16*)p;
    cudaGetSymbolAddress(&p, g_y_lo); __nv_bfloat16* ylo = (__nv_bfloat16*)p;
    cudaGetSymbolAddress(&p, g_h_hi); __nv_bfloat16* hhi = (__nv_bfloat16*)p;
    cudaGetSymbolAddress(&p, g_h_lo); __nv_bfloat16* hlo = (__nv_bfloat16*)p;
    cudaGetSymbolAddress(&p, g_wq_hi); __nv_bfloat16* wqh = (__nv_bfloat16*)p;
    cudaGetSymbolAddress(&p, g_wq_lo); __nv_bfloat16* wql = (__nv_bfloat16*)p;
    cudaGetSymbolAddress(&p, g_wp_hi); __nv_bfloat16* wph = (__nv_bfloat16*)p;
    cudaGetSymbolAddress(&p, g_wp_lo); __nv_bfloat16* wpl = (__nv_bfloat16*)p;
    cudaGetSymbolAddress(&p, g_wf_hi); __nv_bfloat16* wfh = (__nv_bfloat16*)p;
    cudaGetSymbolAddress(&p, g_wf_lo); __nv_bfloat16* wfl = (__nv_bfloat16*)p;
    cudaGetSymbolAddress(&p, g_w2_hi); __nv_bfloat16* w2h = (__nv_bfloat16*)p;
    cudaGetSymbolAddress(&p, g_w2_lo); __nv_bfloat16* w2l = (__nv_bfloat16*)p;

    cudaFuncSetAttribute(hmma_gemm<1>, cudaFuncAttributeMaxDynamicSharedMemorySize, GSMEM);
    cudaFuncSetAttribute(hmma_gemm<2>, cudaFuncAttributeMaxDynamicSharedMemorySize, GSMEM);
    cudaFuncSetAttribute(hmma_gemm<3>, cudaFuncAttributeMaxDynamicSharedMemorySize, GSMEM);
    cudaFuncSetAttribute(attn_hmma, cudaFuncAttributeMaxDynamicSharedMemorySize, ASMEM);

    dim3 wtb(32, 8);
    wt_kernel<<<dim3(C3 / 32,  CEMB / 32), wtb>>>(w_attn, wqh, wql, CEMB, C3);
    wt_kernel<<<dim3(CEMB / 32, CEMB / 32), wtb>>>(w_proj, wph, wpl, CEMB, CEMB);
    wt_kernel<<<dim3(C4 / 32,  CEMB / 32), wtb>>>(w_fc,   wfh, wfl, CEMB, C4);
    wt_kernel<<<dim3(CEMB / 32, C4 / 32),  wtb>>>(w_fc2,  w2h, w2l, C4,   CEMB);

    ln_split_kernel<<<ROWS, 256>>>(x, ln1_g, ln1_b, ahi, alo);
    hmma_gemm<3><<<dim3(C3 / TILE_N, ROWS / TILE_M), 256, GSMEM>>>(
        ahi, alo, wqh, wql, b_attn, nullptr, nullptr, qvh, qvl, ROWS, C3, CEMB);
    attn_hmma<<<dim3(SEQ / AQT, BATCH * NHEAD), 256, ASMEM>>>(qvh, qvl, yhi, ylo);
    hmma_gemm<2><<<dim3(CEMB / TILE_N, ROWS / TILE_M), 256, GSMEM>>>(
        yhi, ylo, wph, wpl, b_proj, x, x2, nullptr, nullptr, ROWS, CEMB, CEMB);
    ln_split_kernel<<<ROWS, 256>>>(x2, ln2_g, ln2_b, ahi, alo);
    hmma_gemm<1><<<dim3(C4 / TILE_N, ROWS / TILE_M), 256, GSMEM>>>(
        ahi, alo, wfh, wfl, b_fc, nullptr, nullptr, hhi, hlo, ROWS, C4, CEMB);
    hmma_gemm<2><<<dim3(CEMB / TILE_N, ROWS / TILE_M), 256, GSMEM>>>(
        hhi, hlo, w2h, w2l, b_fc2, x2, out, nullptr, nullptr, ROWS, CEMB, C4);
}

// round 10
// speedup vs baseline: 1.5977x; 1.5977x over previous
#include <cuda_runtime.h>
#include <cuda_bf16.h>
#include <math.h>
#include <stdint.h>

// ---------------- problem constants ----------------
#define BATCH 4
#define SEQ   2048
#define CEMB  1024
#define NHEAD 16
#define HDIM  64
#define ROWS  (BATCH*SEQ)        // 8192
#define C3    (3*CEMB)           // 3072
#define C4    (4*CEMB)           // 4096

// ---------------- scratch (no cudaMalloc allowed) ----------------
__device__ float g_x2 [(size_t)ROWS*CEMB];
__device__ __nv_bfloat16 g_qkvh[(size_t)ROWS*C3], g_qkvl[(size_t)ROWS*C3];
__device__ __nv_bfloat16 g_a_hi[(size_t)ROWS*CEMB], g_a_lo[(size_t)ROWS*CEMB];
__device__ __nv_bfloat16 g_y_hi[(size_t)ROWS*CEMB], g_y_lo[(size_t)ROWS*CEMB];
__device__ __nv_bfloat16 g_h_hi[(size_t)ROWS*C4],  g_h_lo[(size_t)ROWS*C4];
__device__ __nv_bfloat16 g_wq_hi[(size_t)C3*CEMB],  g_wq_lo[(size_t)C3*CEMB];
__device__ __nv_bfloat16 g_wp_hi[(size_t)CEMB*CEMB],g_wp_lo[(size_t)CEMB*CEMB];
__device__ __nv_bfloat16 g_wf_hi[(size_t)C4*CEMB],  g_wf_lo[(size_t)C4*CEMB];
__device__ __nv_bfloat16 g_w2_hi[(size_t)CEMB*C4],  g_w2_lo[(size_t)CEMB*C4];

// ---------------- PTX helpers (family-safe: cp.async / ldmatrix / mma.sync) ----------------
__device__ __forceinline__ uint32_t s2u(const void* p) {
    uint32_t a;
    asm("{ .reg .u64 t; cvta.to.shared.u64 t, %1; cvt.u32.u64 %0, t; }" : "=r"(a) : "l"(p));
    return a;
}
__device__ __forceinline__ uint32_t swz(uint32_t o) { return o ^ ((o >> 3) & 0x70); }

__device__ __forceinline__ void cp16(uint32_t s, const void* g) {
    asm volatile("cp.async.cg.shared.global [%0], [%1], 16;" :: "r"(s), "l"(g));
}
__device__ __forceinline__ void cp_commit() { asm volatile("cp.async.commit_group;"); }
#define CP_WAIT(N) asm volatile("cp.async.wait_group %0;" :: "n"(N))

__device__ __forceinline__ void ldsm4(uint32_t* r, uint32_t addr) {
    asm volatile("ldmatrix.sync.aligned.m8n8.x4.shared.b16 {%0,%1,%2,%3}, [%4];"
                 : "=r"(r[0]), "=r"(r[1]), "=r"(r[2]), "=r"(r[3]) : "r"(addr));
}
__device__ __forceinline__ void ldsm4t(uint32_t* r, uint32_t addr) {
    asm volatile("ldmatrix.sync.aligned.m8n8.x4.trans.shared.b16 {%0,%1,%2,%3}, [%4];"
                 : "=r"(r[0]), "=r"(r[1]), "=r"(r[2]), "=r"(r[3]) : "r"(addr));
}
__device__ __forceinline__ void mma16816(float* c, const uint32_t* a, const uint32_t* b) {
    asm volatile("mma.sync.aligned.m16n8k16.row.col.f32.bf16.bf16.f32 "
                 "{%0,%1,%2,%3}, {%4,%5,%6,%7}, {%8,%9}, {%0,%1,%2,%3};"
                 : "+f"(c[0]), "+f"(c[1]), "+f"(c[2]), "+f"(c[3])
                 : "r"(a[0]), "r"(a[1]), "r"(a[2]), "r"(a[3]), "r"(b[0]), "r"(b[1]));
}

// ---------------- split helpers ----------------
__device__ __forceinline__ void store_split4(__nv_bfloat16* hip, __nv_bfloat16* lop,
                                             size_t off, float v0, float v1, float v2, float v3) {
    __nv_bfloat162 h0 = __floats2bfloat162_rn(v0, v1);
    __nv_bfloat162 h1 = __floats2bfloat162_rn(v2, v3);
    float l0 = v0 - __low2float(h0),  l1 = v1 - __high2float(h0);
    float l2 = v2 - __low2float(h1),  l3 = v3 - __high2float(h1);
    *reinterpret_cast<__nv_bfloat162*>(hip + off)     = h0;
    *reinterpret_cast<__nv_bfloat162*>(hip + off + 2) = h1;
    *reinterpret_cast<__nv_bfloat162*>(lop + off)     = __floats2bfloat162_rn(l0, l1);
    *reinterpret_cast<__nv_bfloat162*>(lop + off + 2) = __floats2bfloat162_rn(l2, l3);
}
__device__ __forceinline__ void store_split2(__nv_bfloat16* hip, __nv_bfloat16* lop,
                                             size_t off, float v0, float v1) {
    __nv_bfloat162 h = __floats2bfloat162_rn(v0, v1);
    float l0 = v0 - __low2float(h), l1 = v1 - __high2float(h);
    *reinterpret_cast<__nv_bfloat162*>(hip + off) = h;
    *reinterpret_cast<__nv_bfloat162*>(lop + off) = __floats2bfloat162_rn(l0, l1);
}
// pack (x,y) -> bf16x2 hi, residual bf16x2 lo (returned via ref)
__device__ __forceinline__ uint32_t packsplit(float x, float y, uint32_t& lo) {
    __nv_bfloat162 h = __floats2bfloat162_rn(x, y);
    float rx = x - __low2float(h), ry = y - __high2float(h);
    __nv_bfloat162 l = __floats2bfloat162_rn(rx, ry);
    lo = *reinterpret_cast<uint32_t*>(&l);
    return *reinterpret_cast<uint32_t*>(&h);
}

// ---------------- layernorm -> bf16 hi/lo split ----------------
__global__ void ln_split_kernel(const float* __restrict__ x, const float* __restrict__ g,
                                const float* __restrict__ b,
                                __nv_bfloat16* __restrict__ ohi, __nv_bfloat16* __restrict__ olo) {
    int row = blockIdx.x;
    int tid = threadIdx.x;
    const float4 v = ((const float4*)(x + (size_t)row * CEMB))[tid];
    float s  = v.x + v.y + v.z + v.w;
    float sq = v.x * v.x + v.y * v.y + v.z * v.z + v.w * v.w;
    #pragma unroll
    for (int o = 16; o; o >>= 1) {
        s  += __shfl_xor_sync(0xffffffffu, s,  o);
        sq += __shfl_xor_sync(0xffffffffu, sq, o);
    }
    __shared__ float ss[8], sqs[8];
    if ((tid & 31) == 0) { ss[tid >> 5] = s; sqs[tid >> 5] = sq; }
    __syncthreads();
    float tot = 0.f, totq = 0.f;
    #pragma unroll
    for (int w = 0; w < 8; ++w) { tot += ss[w]; totq += sqs[w]; }
    const float mu   = tot * (1.f / CEMB);
    const float var  = totq * (1.f / CEMB) - mu * mu;
    const float rstd = rsqrtf(var + 1e-5f);
    const float4 gg = ((const float4*)g)[tid];
    const float4 bb = ((const float4*)b)[tid];
    float r0 = (v.x - mu) * rstd * gg.x + bb.x;
    float r1 = (v.y - mu) * rstd * gg.y + bb.y;
    float r2 = (v.z - mu) * rstd * gg.z + bb.z;
    float r3 = (v.w - mu) * rstd * gg.w + bb.w;
    store_split4(ohi, olo, (size_t)row * CEMB + tid * 4, r0, r1, r2, r3);
}

// ---------------- weight transpose + split ----------------
__global__ void wt_kernel(const float* __restrict__ w, __nv_bfloat16* __restrict__ whi,
                          __nv_bfloat16* __restrict__ wlo, int K, int N) {
    __shared__ float t[32][33];
    int n0 = blockIdx.x * 32, k0 = blockIdx.y * 32;
    int tx = threadIdx.x, ty = threadIdx.y;
    #pragma unroll
    for (int i = 0; i < 4; ++i)
        t[ty + 8 * i][tx] = w[(size_t)(k0 + ty + 8 * i) * N + n0 + tx];
    __syncthreads();
    #pragma unroll
    for (int i = 0; i < 4; ++i) {
        int r = ty + 8 * i;
        float v = t[tx][r];
        __nv_bfloat16 h = __float2bfloat16(v);
        whi[(size_t)(n0 + r) * K + k0 + tx] = h;
        wlo[(size_t)(n0 + r) * K + k0 + tx] = __float2bfloat16(v - __bfloat162float(h));
    }
}

__device__ __forceinline__ float gelu_t(float v) {
    float u = 0.7978845608028654f * (v + 0.044715f * v * v * v);
    return 0.5f * v * (1.f + tanhf(u));
}

// ---------------- HMMA GEMM; EPI: 1=bias+gelu->split, 2=bias+res->f32, 3=bias->split ----------------
#define TILE_M 128
#define TILE_N 128
#define KCH    64
#define STAGES 4
#define STG_BYTES (TILE_M * 128 + TILE_N * 128)
#define GSMEM (STAGES * STG_BYTES)

template<int EPI>
__global__ __launch_bounds__(256) void hmma_gemm(
    const __nv_bfloat16* __restrict__ Ahi, const __nv_bfloat16* __restrict__ Alo,
    const __nv_bfloat16* __restrict__ Bhi, const __nv_bfloat16* __restrict__ Blo,
    const float* __restrict__ bias, const float* __restrict__ res,
    float* __restrict__ Cf, __nv_bfloat16* __restrict__ Chi, __nv_bfloat16* __restrict__ Clo,
    int M, int N, int K)
{
    extern __shared__ char smem[];
    const uint32_t sb = s2u(smem);
    const int tid = threadIdx.x, wid = tid >> 5, lane = tid & 31;
    const int wm = wid & 1, wn = wid >> 1;
    const int row0 = blockIdx.y * TILE_M, col0 = blockIdx.x * TILE_N;
    const int cpt = K / KCH, NKC = 3 * cpt;

    auto load_chunk = [&](int kc) {
        int s = kc % STAGES;
        int t = kc / cpt;
        int k0 = (kc - t * cpt) * KCH;
        const __nv_bfloat16* A = (t < 2) ? Ahi : Alo;
        const __nv_bfloat16* B = (t == 1) ? Blo : Bhi;
        uint32_t sA = sb + s * STG_BYTES;
        uint32_t sB = sA + TILE_M * 128;
        #pragma unroll
        for (int i = 0; i < 4; ++i) {
            int idx = i * 256 + tid;
            int r = idx >> 3, c = (idx & 7) * 16;
            cp16(sA + swz(r * 128 + c), A + (size_t)(row0 + r) * K + k0 + (c >> 1));
        }
        #pragma unroll
        for (int i = 0; i < 4; ++i) {
            int idx = i * 256 + tid;
            int r = idx >> 3, c = (idx & 7) * 16;
            cp16(sB + swz(r * 128 + c), B + (size_t)(col0 + r) * K + k0 + (c >> 1));
        }
        cp_commit();
    };

    float acc[4][4][4];
    #pragma unroll
    for (int mt = 0; mt < 4; ++mt)
        #pragma unroll
        for (int nt = 0; nt < 4; ++nt)
            #pragma unroll
            for (int q = 0; q < 4; ++q) acc[mt][nt][q] = 0.f;

    for (int kc = 0; kc < STAGES - 1; ++kc) load_chunk(kc);

    const int arow = (lane & 7) + ((lane >> 3) & 1) * 8;
    const int akof = ((lane >> 4) & 1) * 8;
    const int nsel = (lane >> 4) & 1;          // x4 B pairing: which n8 of the pair
    const int bro  = lane & 7;
    const int bk8  = ((lane >> 3) & 1) * 8;

    for (int kc = 0; kc < NKC; ++kc) {
        int s = kc % STAGES;
        CP_WAIT(STAGES - 2);
        __syncthreads();
        if (kc + STAGES - 1 < NKC) load_chunk(kc + STAGES - 1);
        else cp_commit();
        uint32_t sA = sb + s * STG_BYTES;
        uint32_t sB = sA + TILE_M * 128;
        #pragma unroll
        for (int ks = 0; ks < KCH / 16; ++ks) {
            uint32_t a[4][4], b[4][2];
            #pragma unroll
            for (int mt = 0; mt < 4; ++mt) {
                uint32_t o = (uint32_t)(wm * 64 + mt * 16 + arow) * 128 + (ks * 16 + akof) * 2;
                ldsm4(a[mt], sA + swz(o));
            }
            #pragma unroll
            for (int ntp = 0; ntp < 2; ++ntp) {
                uint32_t o = (uint32_t)(wn * 32 + (2 * ntp + nsel) * 8 + bro) * 128 +
                             (ks * 16 + bk8) * 2;
                uint32_t r4[4];
                ldsm4(r4, sB + swz(o));
                b[2 * ntp][0] = r4[0]; b[2 * ntp][1] = r4[1];
                b[2 * ntp + 1][0] = r4[2]; b[2 * ntp + 1][1] = r4[3];
            }
            #pragma unroll
            for (int mt = 0; mt < 4; ++mt)
                #pragma unroll
                for (int nt = 0; nt < 4; ++nt)
                    mma16816(acc[mt][nt], a[mt], b[nt]);
        }
    }

    const int g = lane >> 2, i2 = (lane & 3) * 2;
    #pragma unroll
    for (int mt = 0; mt < 4; ++mt) {
        #pragma unroll
        for (int nt = 0; nt < 4; ++nt) {
            int r = row0 + wm * 64 + mt * 16 + g;
            int c = col0 + wn * 32 + nt * 8 + i2;
            float2 bv = *(const float2*)(bias + c);
            #pragma unroll
            for (int half = 0; half < 2; ++half) {
                int rr = r + half * 8;
                float v0 = acc[mt][nt][half * 2 + 0] + bv.x;
                float v1 = acc[mt][nt][half * 2 + 1] + bv.y;
                if (EPI == 1) {
                    v0 = gelu_t(v0); v1 = gelu_t(v1);
                    store_split2(Chi, Clo, (size_t)rr * N + c, v0, v1);
                } else if (EPI == 3) {
                    store_split2(Chi, Clo, (size_t)rr * N + c, v0, v1);
                } else {
                    if (EPI == 2) {
                        float2 rv = *(const float2*)(res + (size_t)rr * N + c);
                        v0 += rv.x; v1 += rv.y;
                    }
                    float2 ov; ov.x = v0; ov.y = v1;
                    *(float2*)(Cf + (size_t)rr * N + c) = ov;
                }
            }
        }
    }
}

// ---------------- HMMA flash attention v2: Q in smem, P in registers ----------------
// Q tile 128 rows (8 warps x 16), K tile 64. smem: Qh/Ql 32KB + 2 KV stages x 32KB = 96KB.
#define AQT 128
#define AKT 64
#define ASMEM (32768 + 2 * 32768)   // 98304

__global__ __launch_bounds__(256, 2) void attn_hmma(
    const __nv_bfloat16* __restrict__ qkvh, const __nv_bfloat16* __restrict__ qkvl,
    __nv_bfloat16* __restrict__ yhi, __nv_bfloat16* __restrict__ ylo)
{
    extern __shared__ char smem[];
    const uint32_t sb = s2u(smem);
    const int tid = threadIdx.x, wid = tid >> 5, lane = tid & 31;
    const int qb = blockIdx.x, bh = blockIdx.y;
    const int b = bh >> 4, h = bh & 15;
    const int q0 = qb * AQT;
    const size_t rowbase = (size_t)b * SEQ;
    const size_t qcol = (size_t)h * HDIM, kcol = CEMB + qcol, vcol = 2 * CEMB + qcol;

    const uint32_t sQh = sb, sQl = sb + 16384;

    // ---- G0: load Q (hi/lo) into persistent smem region
    #pragma unroll
    for (int i = 0; i < 4; ++i) {
        int idx = i * 256 + tid;
        int r = idx >> 3, c = (idx & 7) * 16;
        size_t grow = (rowbase + q0 + r) * C3 + qcol + (c >> 1);
        cp16(sQh + swz(r * 128 + c), qkvh + grow);
        cp16(sQl + swz(r * 128 + c), qkvl + grow);
    }
    cp_commit();

    auto load_kv = [&](int kt, int s) {
        uint32_t base = sb + 32768 + s * 32768;
        #pragma unroll
        for (int i = 0; i < 2; ++i) {
            int idx = i * 256 + tid;
            int r = idx >> 3, c = (idx & 7) * 16;
            size_t grow = (rowbase + kt * AKT + r) * C3;
            uint32_t so = swz(r * 128 + c);
            cp16(base + so,         qkvh + grow + kcol + (c >> 1));
            cp16(base + 8192 + so,  qkvl + grow + kcol + (c >> 1));
            cp16(base + 16384 + so, qkvh + grow + vcol + (c >> 1));
            cp16(base + 24576 + so, qkvl + grow + vcol + (c >> 1));
        }
        cp_commit();
    };

    const int nkt = 2 * qb + 2;
    load_kv(0, 0);                       // G1
    load_kv(1, 1);                       // G2

    float m0 = -1e30f, m1 = -1e30f, l0 = 0.f, l1 = 0.f;
    float o_[8][4];
    #pragma unroll
    for (int nt = 0; nt < 8; ++nt)
        #pragma unroll
        for (int q = 0; q < 4; ++q) o_[nt][q] = 0.f;

    const int g = lane >> 2;
    const int qr0 = q0 + wid * 16 + g;
    const int ccol = (lane & 3) * 2;
    // A-fragment lane components (Q and packed-P loads)
    const int frow = (lane & 7) + ((lane >> 3) & 1) * 8;
    const int fkof = ((lane >> 4) & 1) * 8;
    // B-fragment x4 pairing lane components (K)
    const int nsel = (lane >> 4) & 1;
    const int bro  = lane & 7;
    const int bk8  = ((lane >> 3) & 1) * 8;
    // V x4 trans components
    const int vrow = lane & 15;
    const int vsel = (lane >> 4) & 1;

    for (int kt = 0; kt < nkt; ++kt) {
        int s = kt & 1;
        CP_WAIT(1);                      // KV tile kt resident (and Q on first iter)
        __syncthreads();
        uint32_t Kh = sb + 32768 + s * 32768;
        uint32_t Kl = Kh + 8192, Vh = Kh + 16384, Vl = Kh + 24576;

        // ---- S = Q K^T (3-term split); Q frags re-loaded from smem (regs stay low)
        float sa[8][4];
        #pragma unroll
        for (int nt = 0; nt < 8; ++nt)
            sa[nt][0] = sa[nt][1] = sa[nt][2] = sa[nt][3] = 0.f;
        #pragma unroll
        for (int ks = 0; ks < 4; ++ks) {
            uint32_t qo = (uint32_t)(wid * 16 + frow) * 128 + (ks * 16 + fkof) * 2;
            uint32_t qh4[4], ql4[4];
            ldsm4(qh4, sQh + swz(qo));
            ldsm4(ql4, sQl + swz(qo));
            #pragma unroll
            for (int ntp = 0; ntp < 4; ++ntp) {
                uint32_t ko = (uint32_t)((2 * ntp + nsel) * 8 + bro) * 128 + (ks * 16 + bk8) * 2;
                uint32_t kh[4], kl[4];
                ldsm4(kh, Kh + swz(ko));
                ldsm4(kl, Kl + swz(ko));
                mma16816(sa[2 * ntp],     qh4, kh);
                mma16816(sa[2 * ntp],     qh4, kl);
                mma16816(sa[2 * ntp],     ql4, kh);
                mma16816(sa[2 * ntp + 1], qh4, kh + 2);
                mma16816(sa[2 * ntp + 1], qh4, kl + 2);
                mma16816(sa[2 * ntp + 1], ql4, kh + 2);
            }
        }

        // ---- scale + causal mask
        const int k0g = kt * AKT;
        const bool tmask = (k0g + AKT - 1) > qr0;
        #pragma unroll
        for (int nt = 0; nt < 8; ++nt) {
            int c0g = k0g + nt * 8 + ccol;
            #pragma unroll
            for (int q = 0; q < 4; ++q) sa[nt][q] *= 0.125f;
            if (tmask) {
                if (c0g > qr0)         sa[nt][0] = -1e30f;
                if (c0g + 1 > qr0)     sa[nt][1] = -1e30f;
                if (c0g > qr0 + 8)     sa[nt][2] = -1e30f;
                if (c0g + 1 > qr0 + 8) sa[nt][3] = -1e30f;
            }
        }

        // ---- online softmax
        float mt0 = -1e30f, mt1 = -1e30f;
        #pragma unroll
        for (int nt = 0; nt < 8; ++nt) {
            mt0 = fmaxf(mt0, fmaxf(sa[nt][0], sa[nt][1]));
            mt1 = fmaxf(mt1, fmaxf(sa[nt][2], sa[nt][3]));
        }
        mt0 = fmaxf(mt0, __shfl_xor_sync(0xffffffffu, mt0, 1));
        mt0 = fmaxf(mt0, __shfl_xor_sync(0xffffffffu, mt0, 2));
        mt1 = fmaxf(mt1, __shfl_xor_sync(0xffffffffu, mt1, 1));
        mt1 = fmaxf(mt1, __shfl_xor_sync(0xffffffffu, mt1, 2));
        float mn0 = fmaxf(m0, mt0), mn1 = fmaxf(m1, mt1);
        float a0 = __expf(m0 - mn0), a1 = __expf(m1 - mn1);
        m0 = mn0; m1 = mn1;
        float rs0 = 0.f, rs1 = 0.f;
        #pragma unroll
        for (int nt = 0; nt < 8; ++nt) {
            sa[nt][0] = __expf(sa[nt][0] - mn0);
            sa[nt][1] = __expf(sa[nt][1] - mn0);
            sa[nt][2] = __expf(sa[nt][2] - mn1);
            sa[nt][3] = __expf(sa[nt][3] - mn1);
            rs0 += sa[nt][0] + sa[nt][1];
            rs1 += sa[nt][2] + sa[nt][3];
        }
        rs0 += __shfl_xor_sync(0xffffffffu, rs0, 1);
        rs0 += __shfl_xor_sync(0xffffffffu, rs0, 2);
        rs1 += __shfl_xor_sync(0xffffffffu, rs1, 1);
        rs1 += __shfl_xor_sync(0xffffffffu, rs1, 2);
        l0 = l0 * a0 + rs0;
        l1 = l1 * a1 + rs1;
        #pragma unroll
        for (int nt = 0; nt < 8; ++nt) {
            o_[nt][0] *= a0; o_[nt][1] *= a0;
            o_[nt][2] *= a1; o_[nt][3] *= a1;
        }

        // ---- pack P into A-fragments in registers (C-frag layout == A-frag layout)
        uint32_t ph[4][4], pl[4][4];
        #pragma unroll
        for (int ks = 0; ks < 4; ++ks) {
            ph[ks][0] = packsplit(sa[2 * ks][0],     sa[2 * ks][1],     pl[ks][0]);
            ph[ks][1] = packsplit(sa[2 * ks][2],     sa[2 * ks][3],     pl[ks][1]);
            ph[ks][2] = packsplit(sa[2 * ks + 1][0], sa[2 * ks + 1][1], pl[ks][2]);
            ph[ks][3] = packsplit(sa[2 * ks + 1][2], sa[2 * ks + 1][3], pl[ks][3]);
        }

        // ---- O += P V (3-term split), V via paired ldmatrix.x4.trans
        #pragma unroll
        for (int ks = 0; ks < 4; ++ks) {
            #pragma unroll
            for (int ntp = 0; ntp < 4; ++ntp) {
                uint32_t vo = (uint32_t)(ks * 16 + vrow) * 128 + (2 * ntp + vsel) * 16;
                uint32_t vh[4], vl[4];
                ldsm4t(vh, Vh + swz(vo));
                ldsm4t(vl, Vl + swz(vo));
                mma16816(o_[2 * ntp],     ph[ks], vh);
                mma16816(o_[2 * ntp],     ph[ks], vl);
                mma16816(o_[2 * ntp],     pl[ks], vh);
                mma16816(o_[2 * ntp + 1], ph[ks], vh + 2);
                mma16816(o_[2 * ntp + 1], ph[ks], vl + 2);
                mma16816(o_[2 * ntp + 1], pl[ks], vh + 2);
            }
        }
        __syncthreads();                  // stage s reusable
        if (kt + 2 < nkt) load_kv(kt + 2, s);
        else cp_commit();                 // uniform group accounting
    }

    // ---- epilogue: y = O / l, split bf16
    float i0 = 1.f / l0, i1 = 1.f / l1;
    #pragma unroll
    for (int nt = 0; nt < 8; ++nt) {
        size_t col = qcol + nt * 8 + ccol;
        store_split2(yhi, ylo, (rowbase + qr0) * CEMB + col,     o_[nt][0] * i0, o_[nt][1] * i0);
        store_split2(yhi, ylo, (rowbase + qr0 + 8) * CEMB + col, o_[nt][2] * i1, o_[nt][3] * i1);
    }
}

// ---------------- launch ----------------
extern "C" void kernel_launch(void* const* d_in, const int* in_sizes, int n_in,
                              void* d_out, int out_size) {
    const float* x      = (const float*)d_in[0];
    const float* ln1_g  = (const float*)d_in[1];
    const float* ln1_b  = (const float*)d_in[2];
    const float* w_attn = (const float*)d_in[3];
    const float* b_attn = (const float*)d_in[4];
    const float* w_proj = (const float*)d_in[5];
    const float* b_proj = (const float*)d_in[6];
    const float* ln2_g  = (const float*)d_in[7];
    const float* ln2_b  = (const float*)d_in[8];
    const float* w_fc   = (const float*)d_in[9];
    const float* b_fc   = (const float*)d_in[10];
    const float* w_fc2  = (const float*)d_in[11];
    const float* b_fc2  = (const float*)d_in[12];
    float* out = (float*)d_out;

    void* p;
    cudaGetSymbolAddress(&p, g_x2);   float* x2  = (float*)p;
    cudaGetSymbolAddress(&p, g_qkvh); __nv_bfloat16* qvh = (__nv_bfloat16*)p;
    cudaGetSymbolAddress(&p, g_qkvl); __nv_bfloat16* qvl = (__nv_bfloat16*)p;
    cudaGetSymbolAddress(&p, g_a_hi); __nv_bfloat16* ahi = (__nv_bfloat16*)p;
    cudaGetSymbolAddress(&p, g_a_lo); __nv_bfloat16* alo = (__nv_bfloat16*)p;
    cudaGetSymbolAddress(&p, g_y_hi); __nv_bfloat16* yhi = (__nv_bfloat16*)p;
    cudaGetSymbolAddress(&p, g_y_lo); __nv_bfloat16* ylo = (__nv_bfloat16*)p;
    cudaGetSymbolAddress(&p, g_h_hi); __nv_bfloat16* hhi = (__nv_bfloat16*)p;
    cudaGetSymbolAddress(&p, g_h_lo); __nv_bfloat16* hlo = (__nv_bfloat16*)p;
    cudaGetSymbolAddress(&p, g_wq_hi); __nv_bfloat16* wqh = (__nv_bfloat16*)p;
    cudaGetSymbolAddress(&p, g_wq_lo); __nv_bfloat16* wql = (__nv_bfloat16*)p;
    cudaGetSymbolAddress(&p, g_wp_hi); __nv_bfloat16* wph = (__nv_bfloat16*)p;
    cudaGetSymbolAddress(&p, g_wp_lo); __nv_bfloat16* wpl = (__nv_bfloat16*)p;
    cudaGetSymbolAddress(&p, g_wf_hi); __nv_bfloat16* wfh = (__nv_bfloat16*)p;
    cudaGetSymbolAddress(&p, g_wf_lo); __nv_bfloat16* wfl = (__nv_bfloat16*)p;
    cudaGetSymbolAddress(&p, g_w2_hi); __nv_bfloat16* w2h = (__nv_bfloat16*)p;
    cudaGetSymbolAddress(&p, g_w2_lo); __nv_bfloat16* w2l = (__nv_bfloat16*)p;

    cudaFuncSetAttribute(hmma_gemm<1>, cudaFuncAttributeMaxDynamicSharedMemorySize, GSMEM);
    cudaFuncSetAttribute(hmma_gemm<2>, cudaFuncAttributeMaxDynamicSharedMemorySize, GSMEM);
    cudaFuncSetAttribute(hmma_gemm<3>, cudaFuncAttributeMaxDynamicSharedMemorySize, GSMEM);
    cudaFuncSetAttribute(attn_hmma, cudaFuncAttributeMaxDynamicSharedMemorySize, ASMEM);

    dim3 wtb(32, 8);
    wt_kernel<<<dim3(C3 / 32,  CEMB / 32), wtb>>>(w_attn, wqh, wql, CEMB, C3);
    wt_kernel<<<dim3(CEMB / 32, CEMB / 32), wtb>>>(w_proj, wph, wpl, CEMB, CEMB);
    wt_kernel<<<dim3(C4 / 32,  CEMB / 32), wtb>>>(w_fc,   wfh, wfl, CEMB, C4);
    wt_kernel<<<dim3(CEMB / 32, C4 / 32),  wtb>>>(w_fc2,  w2h, w2l, C4,   CEMB);

    ln_split_kernel<<<ROWS, 256>>>(x, ln1_g, ln1_b, ahi, alo);
    hmma_gemm<3><<<dim3(C3 / TILE_N, ROWS / TILE_M), 256, GSMEM>>>(
        ahi, alo, wqh, wql, b_attn, nullptr, nullptr, qvh, qvl, ROWS, C3, CEMB);
    attn_hmma<<<dim3(SEQ / AQT, BATCH * NHEAD), 256, ASMEM>>>(qvh, qvl, yhi, ylo);
    hmma_gemm<2><<<dim3(CEMB / TILE_N, ROWS / TILE_M), 256, GSMEM>>>(
        yhi, ylo, wph, wpl, b_proj, x, x2, nullptr, nullptr, ROWS, CEMB, CEMB);
    ln_split_kernel<<<ROWS, 256>>>(x2, ln2_g, ln2_b, ahi, alo);
    hmma_gemm<1><<<dim3(C4 / TILE_N, ROWS / TILE_M), 256, GSMEM>>>(
        ahi, alo, wfh, wfl, b_fc, nullptr, nullptr, hhi, hlo, ROWS, C4, CEMB);
    hmma_gemm<2><<<dim3(CEMB / TILE_N, ROWS / TILE_M), 256, GSMEM>>>(
        hhi, hlo, w2h, w2l, b_fc2, x2, out, nullptr, nullptr, ROWS, CEMB, C4);
}

// round 11
// speedup vs baseline: 4.2497x; 2.6598x over previous
#include <cuda_runtime.h>
#include <cuda_bf16.h>
#include <cuda_fp16.h>
#include <math.h>
#include <stdint.h>

// ---------------- problem constants ----------------
#define BATCH 4
#define SEQ   2048
#define CEMB  1024
#define NHEAD 16
#define HDIM  64
#define ROWS  (BATCH*SEQ)        // 8192
#define C3    (3*CEMB)           // 3072
#define C4    (4*CEMB)           // 4096

// ---------------- scratch (no cudaMalloc allowed) ----------------
__device__ float  g_x2 [(size_t)ROWS*CEMB];
__device__ __half g_qkv[(size_t)ROWS*C3];
__device__ __half g_a  [(size_t)ROWS*CEMB];
__device__ __half g_y  [(size_t)ROWS*CEMB];
__device__ __half g_h  [(size_t)ROWS*C4];
__device__ __half g_wq [(size_t)C3*CEMB];
__device__ __half g_wp [(size_t)CEMB*CEMB];
__device__ __half g_wf [(size_t)C4*CEMB];
__device__ __half g_w2 [(size_t)CEMB*C4];

// ---------------- PTX helpers (family-safe: cp.async / ldmatrix / mma.sync) ----------------
__device__ __forceinline__ uint32_t s2u(const void* p) {
    uint32_t a;
    asm("{ .reg .u64 t; cvta.to.shared.u64 t, %1; cvt.u32.u64 %0, t; }" : "=r"(a) : "l"(p));
    return a;
}
__device__ __forceinline__ uint32_t swz(uint32_t o) { return o ^ ((o >> 3) & 0x70); }

__device__ __forceinline__ void cp16(uint32_t s, const void* g) {
    asm volatile("cp.async.cg.shared.global [%0], [%1], 16;" :: "r"(s), "l"(g));
}
__device__ __forceinline__ void cp_commit() { asm volatile("cp.async.commit_group;"); }
#define CP_WAIT(N) asm volatile("cp.async.wait_group %0;" :: "n"(N))

__device__ __forceinline__ void ldsm4(uint32_t* r, uint32_t addr) {
    asm volatile("ldmatrix.sync.aligned.m8n8.x4.shared.b16 {%0,%1,%2,%3}, [%4];"
                 : "=r"(r[0]), "=r"(r[1]), "=r"(r[2]), "=r"(r[3]) : "r"(addr));
}
__device__ __forceinline__ void ldsm4t(uint32_t* r, uint32_t addr) {
    asm volatile("ldmatrix.sync.aligned.m8n8.x4.trans.shared.b16 {%0,%1,%2,%3}, [%4];"
                 : "=r"(r[0]), "=r"(r[1]), "=r"(r[2]), "=r"(r[3]) : "r"(addr));
}
// fp16 inputs, fp32 accumulate
__device__ __forceinline__ void mma16816(float* c, const uint32_t* a, const uint32_t* b) {
    asm volatile("mma.sync.aligned.m16n8k16.row.col.f32.f16.f16.f32 "
                 "{%0,%1,%2,%3}, {%4,%5,%6,%7}, {%8,%9}, {%0,%1,%2,%3};"
                 : "+f"(c[0]), "+f"(c[1]), "+f"(c[2]), "+f"(c[3])
                 : "r"(a[0]), "r"(a[1]), "r"(a[2]), "r"(a[3]), "r"(b[0]), "r"(b[1]));
}

__device__ __forceinline__ uint32_t packh2(float x, float y) {
    __half2 h = __floats2half2_rn(x, y);
    return *reinterpret_cast<uint32_t*>(&h);
}
__device__ __forceinline__ void store_h2(__half* p, size_t off, float v0, float v1) {
    __half2 h = __floats2half2_rn(v0, v1);
    *reinterpret_cast<__half2*>(p + off) = h;
}

// ---------------- layernorm -> fp16 ----------------
__global__ void ln_h_kernel(const float* __restrict__ x, const float* __restrict__ g,
                            const float* __restrict__ b, __half* __restrict__ oh) {
    int row = blockIdx.x;
    int tid = threadIdx.x;
    const float4 v = ((const float4*)(x + (size_t)row * CEMB))[tid];
    float s  = v.x + v.y + v.z + v.w;
    float sq = v.x * v.x + v.y * v.y + v.z * v.z + v.w * v.w;
    #pragma unroll
    for (int o = 16; o; o >>= 1) {
        s  += __shfl_xor_sync(0xffffffffu, s,  o);
        sq += __shfl_xor_sync(0xffffffffu, sq, o);
    }
    __shared__ float ss[8], sqs[8];
    if ((tid & 31) == 0) { ss[tid >> 5] = s; sqs[tid >> 5] = sq; }
    __syncthreads();
    float tot = 0.f, totq = 0.f;
    #pragma unroll
    for (int w = 0; w < 8; ++w) { tot += ss[w]; totq += sqs[w]; }
    const float mu   = tot * (1.f / CEMB);
    const float var  = totq * (1.f / CEMB) - mu * mu;
    const float rstd = rsqrtf(var + 1e-5f);
    const float4 gg = ((const float4*)g)[tid];
    const float4 bb = ((const float4*)b)[tid];
    size_t off = (size_t)row * CEMB + tid * 4;
    store_h2(oh, off,     (v.x - mu) * rstd * gg.x + bb.x, (v.y - mu) * rstd * gg.y + bb.y);
    store_h2(oh, off + 2, (v.z - mu) * rstd * gg.z + bb.z, (v.w - mu) * rstd * gg.w + bb.w);
}

// ---------------- weight transpose: w[K,N] f32 -> [N,K] fp16 ----------------
__global__ void wt_kernel(const float* __restrict__ w, __half* __restrict__ wh, int K, int N) {
    __shared__ float t[32][33];
    int n0 = blockIdx.x * 32, k0 = blockIdx.y * 32;
    int tx = threadIdx.x, ty = threadIdx.y;
    #pragma unroll
    for (int i = 0; i < 4; ++i)
        t[ty + 8 * i][tx] = w[(size_t)(k0 + ty + 8 * i) * N + n0 + tx];
    __syncthreads();
    #pragma unroll
    for (int i = 0; i < 4; ++i) {
        int r = ty + 8 * i;
        wh[(size_t)(n0 + r) * K + k0 + tx] = __float2half(t[tx][r]);
    }
}

__device__ __forceinline__ float gelu_t(float v) {
    float u = 0.7978845608028654f * (v + 0.044715f * v * v * v);
    return 0.5f * v * (1.f + tanhf(u));
}

// ---------------- HMMA GEMM (fp16 single-pass); EPI: 1=bias+gelu->h, 2=bias+res->f32, 3=bias->h ----------------
#define TILE_M 128
#define TILE_N 128
#define KCH    64
#define STAGES 4
#define STG_BYTES (TILE_M * 128 + TILE_N * 128)
#define GSMEM (STAGES * STG_BYTES)

template<int EPI>
__global__ __launch_bounds__(256) void hmma_gemm(
    const __half* __restrict__ A, const __half* __restrict__ B,
    const float* __restrict__ bias, const float* __restrict__ res,
    float* __restrict__ Cf, __half* __restrict__ Ch,
    int M, int N, int K)
{
    extern __shared__ char smem[];
    const uint32_t sb = s2u(smem);
    const int tid = threadIdx.x, wid = tid >> 5, lane = tid & 31;
    const int wm = wid & 1, wn = wid >> 1;
    const int row0 = blockIdx.y * TILE_M, col0 = blockIdx.x * TILE_N;
    const int NKC = K / KCH;

    auto load_chunk = [&](int kc) {
        int s = kc % STAGES;
        int k0 = kc * KCH;
        uint32_t sA = sb + s * STG_BYTES;
        uint32_t sB = sA + TILE_M * 128;
        #pragma unroll
        for (int i = 0; i < 4; ++i) {
            int idx = i * 256 + tid;
            int r = idx >> 3, c = (idx & 7) * 16;
            cp16(sA + swz(r * 128 + c), A + (size_t)(row0 + r) * K + k0 + (c >> 1));
        }
        #pragma unroll
        for (int i = 0; i < 4; ++i) {
            int idx = i * 256 + tid;
            int r = idx >> 3, c = (idx & 7) * 16;
            cp16(sB + swz(r * 128 + c), B + (size_t)(col0 + r) * K + k0 + (c >> 1));
        }
        cp_commit();
    };

    float acc[4][4][4];
    #pragma unroll
    for (int mt = 0; mt < 4; ++mt)
        #pragma unroll
        for (int nt = 0; nt < 4; ++nt)
            #pragma unroll
            for (int q = 0; q < 4; ++q) acc[mt][nt][q] = 0.f;

    for (int kc = 0; kc < STAGES - 1; ++kc) load_chunk(kc);

    const int arow = (lane & 7) + ((lane >> 3) & 1) * 8;
    const int akof = ((lane >> 4) & 1) * 8;
    const int nsel = (lane >> 4) & 1;
    const int bro  = lane & 7;
    const int bk8  = ((lane >> 3) & 1) * 8;

    for (int kc = 0; kc < NKC; ++kc) {
        int s = kc % STAGES;
        CP_WAIT(STAGES - 2);
        __syncthreads();
        if (kc + STAGES - 1 < NKC) load_chunk(kc + STAGES - 1);
        else cp_commit();
        uint32_t sA = sb + s * STG_BYTES;
        uint32_t sB = sA + TILE_M * 128;
        #pragma unroll
        for (int ks = 0; ks < KCH / 16; ++ks) {
            uint32_t a[4][4], b[4][2];
            #pragma unroll
            for (int mt = 0; mt < 4; ++mt) {
                uint32_t o = (uint32_t)(wm * 64 + mt * 16 + arow) * 128 + (ks * 16 + akof) * 2;
                ldsm4(a[mt], sA + swz(o));
            }
            #pragma unroll
            for (int ntp = 0; ntp < 2; ++ntp) {
                uint32_t o = (uint32_t)(wn * 32 + (2 * ntp + nsel) * 8 + bro) * 128 +
                             (ks * 16 + bk8) * 2;
                uint32_t r4[4];
                ldsm4(r4, sB + swz(o));
                b[2 * ntp][0] = r4[0]; b[2 * ntp][1] = r4[1];
                b[2 * ntp + 1][0] = r4[2]; b[2 * ntp + 1][1] = r4[3];
            }
            #pragma unroll
            for (int mt = 0; mt < 4; ++mt)
                #pragma unroll
                for (int nt = 0; nt < 4; ++nt)
                    mma16816(acc[mt][nt], a[mt], b[nt]);
        }
    }

    const int g = lane >> 2, i2 = (lane & 3) * 2;
    #pragma unroll
    for (int mt = 0; mt < 4; ++mt) {
        #pragma unroll
        for (int nt = 0; nt < 4; ++nt) {
            int r = row0 + wm * 64 + mt * 16 + g;
            int c = col0 + wn * 32 + nt * 8 + i2;
            float2 bv = *(const float2*)(bias + c);
            #pragma unroll
            for (int half = 0; half < 2; ++half) {
                int rr = r + half * 8;
                float v0 = acc[mt][nt][half * 2 + 0] + bv.x;
                float v1 = acc[mt][nt][half * 2 + 1] + bv.y;
                if (EPI == 1) {
                    store_h2(Ch, (size_t)rr * N + c, gelu_t(v0), gelu_t(v1));
                } else if (EPI == 3) {
                    store_h2(Ch, (size_t)rr * N + c, v0, v1);
                } else {
                    float2 rv = *(const float2*)(res + (size_t)rr * N + c);
                    float2 ov; ov.x = v0 + rv.x; ov.y = v1 + rv.y;
                    *(float2*)(Cf + (size_t)rr * N + c) = ov;
                }
            }
        }
    }
}

// ---------------- HMMA flash attention (fp16 single-pass) ----------------
// Q tile 128 (8 warps x 16 rows), K tile 64. smem: Q 16KB + 2 stages x 16KB = 48KB.
#define AQT 128
#define AKT 64
#define ASMEM (16384 + 2 * 16384)   // 49152

__global__ __launch_bounds__(256, 2) void attn_hmma(
    const __half* __restrict__ qkv, __half* __restrict__ y)
{
    extern __shared__ char smem[];
    const uint32_t sb = s2u(smem);
    const int tid = threadIdx.x, wid = tid >> 5, lane = tid & 31;
    const int qb = blockIdx.x, bh = blockIdx.y;
    const int b = bh >> 4, h = bh & 15;
    const int q0 = qb * AQT;
    const size_t rowbase = (size_t)b * SEQ;
    const size_t qcol = (size_t)h * HDIM, kcol = CEMB + qcol, vcol = 2 * CEMB + qcol;

    const uint32_t sQ = sb;

    // G0: Q tile (16KB)
    #pragma unroll
    for (int i = 0; i < 4; ++i) {
        int idx = i * 256 + tid;
        int r = idx >> 3, c = (idx & 7) * 16;
        cp16(sQ + swz(r * 128 + c), qkv + (rowbase + q0 + r) * C3 + qcol + (c >> 1));
    }
    cp_commit();

    auto load_kv = [&](int kt, int s) {
        uint32_t base = sb + 16384 + s * 16384;
        #pragma unroll
        for (int i = 0; i < 2; ++i) {
            int idx = i * 256 + tid;
            int r = idx >> 3, c = (idx & 7) * 16;
            size_t grow = (rowbase + kt * AKT + r) * C3;
            uint32_t so = swz(r * 128 + c);
            cp16(base + so,        qkv + grow + kcol + (c >> 1));
            cp16(base + 8192 + so, qkv + grow + vcol + (c >> 1));
        }
        cp_commit();
    };

    const int nkt = 2 * qb + 2;
    load_kv(0, 0);
    load_kv(1, 1);

    float m0 = -1e30f, m1 = -1e30f, l0 = 0.f, l1 = 0.f;
    float o_[8][4];
    #pragma unroll
    for (int nt = 0; nt < 8; ++nt)
        #pragma unroll
        for (int q = 0; q < 4; ++q) o_[nt][q] = 0.f;

    const int g = lane >> 2;
    const int qr0 = q0 + wid * 16 + g;
    const int ccol = (lane & 3) * 2;
    const int frow = (lane & 7) + ((lane >> 3) & 1) * 8;
    const int fkof = ((lane >> 4) & 1) * 8;
    const int nsel = (lane >> 4) & 1;
    const int bro  = lane & 7;
    const int bk8  = ((lane >> 3) & 1) * 8;
    const int vrow = lane & 15;
    const int vsel = (lane >> 4) & 1;

    for (int kt = 0; kt < nkt; ++kt) {
        int s = kt & 1;
        CP_WAIT(1);
        __syncthreads();
        uint32_t K_ = sb + 16384 + s * 16384;
        uint32_t V_ = K_ + 8192;

        // S = Q K^T
        float sa[8][4];
        #pragma unroll
        for (int nt = 0; nt < 8; ++nt)
            sa[nt][0] = sa[nt][1] = sa[nt][2] = sa[nt][3] = 0.f;
        #pragma unroll
        for (int ks = 0; ks < 4; ++ks) {
            uint32_t qo = (uint32_t)(wid * 16 + frow) * 128 + (ks * 16 + fkof) * 2;
            uint32_t q4[4];
            ldsm4(q4, sQ + swz(qo));
            #pragma unroll
            for (int ntp = 0; ntp < 4; ++ntp) {
                uint32_t ko = (uint32_t)((2 * ntp + nsel) * 8 + bro) * 128 + (ks * 16 + bk8) * 2;
                uint32_t k4[4];
                ldsm4(k4, K_ + swz(ko));
                mma16816(sa[2 * ntp],     q4, k4);
                mma16816(sa[2 * ntp + 1], q4, k4 + 2);
            }
        }

        // scale + causal mask
        const int k0g = kt * AKT;
        const bool tmask = (k0g + AKT - 1) > qr0;
        #pragma unroll
        for (int nt = 0; nt < 8; ++nt) {
            int c0g = k0g + nt * 8 + ccol;
            #pragma unroll
            for (int q = 0; q < 4; ++q) sa[nt][q] *= 0.125f;
            if (tmask) {
                if (c0g > qr0)         sa[nt][0] = -1e30f;
                if (c0g + 1 > qr0)     sa[nt][1] = -1e30f;
                if (c0g > qr0 + 8)     sa[nt][2] = -1e30f;
                if (c0g + 1 > qr0 + 8) sa[nt][3] = -1e30f;
            }
        }

        // online softmax
        float mt0 = -1e30f, mt1 = -1e30f;
        #pragma unroll
        for (int nt = 0; nt < 8; ++nt) {
            mt0 = fmaxf(mt0, fmaxf(sa[nt][0], sa[nt][1]));
            mt1 = fmaxf(mt1, fmaxf(sa[nt][2], sa[nt][3]));
        }
        mt0 = fmaxf(mt0, __shfl_xor_sync(0xffffffffu, mt0, 1));
        mt0 = fmaxf(mt0, __shfl_xor_sync(0xffffffffu, mt0, 2));
        mt1 = fmaxf(mt1, __shfl_xor_sync(0xffffffffu, mt1, 1));
        mt1 = fmaxf(mt1, __shfl_xor_sync(0xffffffffu, mt1, 2));
        float mn0 = fmaxf(m0, mt0), mn1 = fmaxf(m1, mt1);
        float a0 = __expf(m0 - mn0), a1 = __expf(m1 - mn1);
        m0 = mn0; m1 = mn1;
        float rs0 = 0.f, rs1 = 0.f;
        #pragma unroll
        for (int nt = 0; nt < 8; ++nt) {
            sa[nt][0] = __expf(sa[nt][0] - mn0);
            sa[nt][1] = __expf(sa[nt][1] - mn0);
            sa[nt][2] = __expf(sa[nt][2] - mn1);
            sa[nt][3] = __expf(sa[nt][3] - mn1);
            rs0 += sa[nt][0] + sa[nt][1];
            rs1 += sa[nt][2] + sa[nt][3];
        }
        rs0 += __shfl_xor_sync(0xffffffffu, rs0, 1);
        rs0 += __shfl_xor_sync(0xffffffffu, rs0, 2);
        rs1 += __shfl_xor_sync(0xffffffffu, rs1, 1);
        rs1 += __shfl_xor_sync(0xffffffffu, rs1, 2);
        l0 = l0 * a0 + rs0;
        l1 = l1 * a1 + rs1;
        #pragma unroll
        for (int nt = 0; nt < 8; ++nt) {
            o_[nt][0] *= a0; o_[nt][1] *= a0;
            o_[nt][2] *= a1; o_[nt][3] *= a1;
        }

        // pack P to fp16 A-fragments in registers
        uint32_t ph[4][4];
        #pragma unroll
        for (int ks = 0; ks < 4; ++ks) {
            ph[ks][0] = packh2(sa[2 * ks][0],     sa[2 * ks][1]);
            ph[ks][1] = packh2(sa[2 * ks][2],     sa[2 * ks][3]);
            ph[ks][2] = packh2(sa[2 * ks + 1][0], sa[2 * ks + 1][1]);
            ph[ks][3] = packh2(sa[2 * ks + 1][2], sa[2 * ks + 1][3]);
        }

        // O += P V, V via paired ldmatrix.x4.trans
        #pragma unroll
        for (int ks = 0; ks < 4; ++ks) {
            #pragma unroll
            for (int ntp = 0; ntp < 4; ++ntp) {
                uint32_t vo = (uint32_t)(ks * 16 + vrow) * 128 + (2 * ntp + vsel) * 16;
                uint32_t v4[4];
                ldsm4t(v4, V_ + swz(vo));
                mma16816(o_[2 * ntp],     ph[ks], v4);
                mma16816(o_[2 * ntp + 1], ph[ks], v4 + 2);
            }
        }
        __syncthreads();
        if (kt + 2 < nkt) load_kv(kt + 2, s);
        else cp_commit();
    }

    // epilogue: y = O / l -> fp16
    float i0 = 1.f / l0, i1 = 1.f / l1;
    #pragma unroll
    for (int nt = 0; nt < 8; ++nt) {
        size_t col = qcol + nt * 8 + ccol;
        store_h2(y, (rowbase + qr0) * CEMB + col,     o_[nt][0] * i0, o_[nt][1] * i0);
        store_h2(y, (rowbase + qr0 + 8) * CEMB + col, o_[nt][2] * i1, o_[nt][3] * i1);
    }
}

// ---------------- launch ----------------
extern "C" void kernel_launch(void* const* d_in, const int* in_sizes, int n_in,
                              void* d_out, int out_size) {
    const float* x      = (const float*)d_in[0];
    const float* ln1_g  = (const float*)d_in[1];
    const float* ln1_b  = (const float*)d_in[2];
    const float* w_attn = (const float*)d_in[3];
    const float* b_attn = (const float*)d_in[4];
    const float* w_proj = (const float*)d_in[5];
    const float* b_proj = (const float*)d_in[6];
    const float* ln2_g  = (const float*)d_in[7];
    const float* ln2_b  = (const float*)d_in[8];
    const float* w_fc   = (const float*)d_in[9];
    const float* b_fc   = (const float*)d_in[10];
    const float* w_fc2  = (const float*)d_in[11];
    const float* b_fc2  = (const float*)d_in[12];
    float* out = (float*)d_out;

    void* p;
    cudaGetSymbolAddress(&p, g_x2);  float* x2  = (float*)p;
    cudaGetSymbolAddress(&p, g_qkv); __half* qv = (__half*)p;
    cudaGetSymbolAddress(&p, g_a);   __half* ah = (__half*)p;
    cudaGetSymbolAddress(&p, g_y);   __half* yh = (__half*)p;
    cudaGetSymbolAddress(&p, g_h);   __half* hh = (__half*)p;
    cudaGetSymbolAddress(&p, g_wq);  __half* wq = (__half*)p;
    cudaGetSymbolAddress(&p, g_wp);  __half* wp = (__half*)p;
    cudaGetSymbolAddress(&p, g_wf);  __half* wf = (__half*)p;
    cudaGetSymbolAddress(&p, g_w2);  __half* w2 = (__half*)p;

    cudaFuncSetAttribute(hmma_gemm<1>, cudaFuncAttributeMaxDynamicSharedMemorySize, GSMEM);
    cudaFuncSetAttribute(hmma_gemm<2>, cudaFuncAttributeMaxDynamicSharedMemorySize, GSMEM);
    cudaFuncSetAttribute(hmma_gemm<3>, cudaFuncAttributeMaxDynamicSharedMemorySize, GSMEM);
    cudaFuncSetAttribute(attn_hmma, cudaFuncAttributeMaxDynamicSharedMemorySize, ASMEM);

    dim3 wtb(32, 8);
    wt_kernel<<<dim3(C3 / 32,  CEMB / 32), wtb>>>(w_attn, wq, CEMB, C3);
    wt_kernel<<<dim3(CEMB / 32, CEMB / 32), wtb>>>(w_proj, wp, CEMB, CEMB);
    wt_kernel<<<dim3(C4 / 32,  CEMB / 32), wtb>>>(w_fc,   wf, CEMB, C4);
    wt_kernel<<<dim3(CEMB / 32, C4 / 32),  wtb>>>(w_fc2,  w2, C4,   CEMB);

    // 1) ln1(x) -> fp16
    ln_h_kernel<<<ROWS, 256>>>(x, ln1_g, ln1_b, ah);
    // 2) qkv = ln1 @ w_attn + b_attn -> fp16
    hmma_gemm<3><<<dim3(C3 / TILE_N, ROWS / TILE_M), 256, GSMEM>>>(
        ah, wq, b_attn, nullptr, nullptr, qv, ROWS, C3, CEMB);
    // 3) attention -> fp16 y
    attn_hmma<<<dim3(SEQ / AQT, BATCH * NHEAD), 256, ASMEM>>>(qv, yh);
    // 4) x2 = x + y @ w_proj + b_proj (f32)
    hmma_gemm<2><<<dim3(CEMB / TILE_N, ROWS / TILE_M), 256, GSMEM>>>(
        yh, wp, b_proj, x, x2, nullptr, ROWS, CEMB, CEMB);
    // 5) ln2(x2) -> fp16
    ln_h_kernel<<<ROWS, 256>>>(x2, ln2_g, ln2_b, ah);
    // 6) h = gelu(ln2 @ w_fc + b_fc) -> fp16
    hmma_gemm<1><<<dim3(C4 / TILE_N, ROWS / TILE_M), 256, GSMEM>>>(
        ah, wf, b_fc, nullptr, nullptr, hh, ROWS, C4, CEMB);
    // 7) out = x2 + h @ w_fc2 + b_fc2 (f32)
    hmma_gemm<2><<<dim3(CEMB / TILE_N, ROWS / TILE_M), 256, GSMEM>>>(
        hh, w2, b_fc2, x2, out, nullptr, ROWS, CEMB, C4);
}

// round 14
// speedup vs baseline: 4.6229x; 1.0878x over previous
#include <cuda_runtime.h>
#include <cuda_bf16.h>
#include <cuda_fp16.h>
#include <math.h>
#include <stdint.h>

// ---------------- problem constants ----------------
#define BATCH 4
#define SEQ   2048
#define CEMB  1024
#define NHEAD 16
#define HDIM  64
#define ROWS  (BATCH*SEQ)        // 8192
#define C3    (3*CEMB)           // 3072
#define C4    (4*CEMB)           // 4096

// ---------------- scratch (no cudaMalloc allowed) ----------------
__device__ float  g_x2 [(size_t)ROWS*CEMB];
__device__ __half g_qkv[(size_t)ROWS*C3];
__device__ __half g_a  [(size_t)ROWS*CEMB];
__device__ __half g_y  [(size_t)ROWS*CEMB];
__device__ __half g_h  [(size_t)ROWS*C4];
__device__ __half g_wq [(size_t)C3*CEMB];
__device__ __half g_wp [(size_t)CEMB*CEMB];
__device__ __half g_wf [(size_t)C4*CEMB];
__device__ __half g_w2 [(size_t)CEMB*C4];

// ---------------- PTX helpers (family-safe: cp.async / ldmatrix / mma.sync) ----------------
__device__ __forceinline__ uint32_t s2u(const void* p) {
    uint32_t a;
    asm("{ .reg .u64 t; cvta.to.shared.u64 t, %1; cvt.u32.u64 %0, t; }" : "=r"(a) : "l"(p));
    return a;
}
__device__ __forceinline__ uint32_t swz(uint32_t o) { return o ^ ((o >> 3) & 0x70); }

__device__ __forceinline__ void cp16(uint32_t s, const void* g) {
    asm volatile("cp.async.cg.shared.global [%0], [%1], 16;" :: "r"(s), "l"(g));
}
__device__ __forceinline__ void cp_commit() { asm volatile("cp.async.commit_group;"); }
#define CP_WAIT(N) asm volatile("cp.async.wait_group %0;" :: "n"(N))

__device__ __forceinline__ void ldsm4(uint32_t* r, uint32_t addr) {
    asm volatile("ldmatrix.sync.aligned.m8n8.x4.shared.b16 {%0,%1,%2,%3}, [%4];"
                 : "=r"(r[0]), "=r"(r[1]), "=r"(r[2]), "=r"(r[3]) : "r"(addr));
}
__device__ __forceinline__ void ldsm4t(uint32_t* r, uint32_t addr) {
    asm volatile("ldmatrix.sync.aligned.m8n8.x4.trans.shared.b16 {%0,%1,%2,%3}, [%4];"
                 : "=r"(r[0]), "=r"(r[1]), "=r"(r[2]), "=r"(r[3]) : "r"(addr));
}
// fp16 inputs, fp32 accumulate
__device__ __forceinline__ void mma16816(float* c, const uint32_t* a, const uint32_t* b) {
    asm volatile("mma.sync.aligned.m16n8k16.row.col.f32.f16.f16.f32 "
                 "{%0,%1,%2,%3}, {%4,%5,%6,%7}, {%8,%9}, {%0,%1,%2,%3};"
                 : "+f"(c[0]), "+f"(c[1]), "+f"(c[2]), "+f"(c[3])
                 : "r"(a[0]), "r"(a[1]), "r"(a[2]), "r"(a[3]), "r"(b[0]), "r"(b[1]));
}

__device__ __forceinline__ uint32_t packh2(float x, float y) {
    __half2 h = __floats2half2_rn(x, y);
    return *reinterpret_cast<uint32_t*>(&h);
}
__device__ __forceinline__ void store_h2(__half* p, size_t off, float v0, float v1) {
    __half2 h = __floats2half2_rn(v0, v1);
    *reinterpret_cast<__half2*>(p + off) = h;
}

// ---------------- layernorm -> fp16 ----------------
__global__ void ln_h_kernel(const float* __restrict__ x, const float* __restrict__ g,
                            const float* __restrict__ b, __half* __restrict__ oh) {
    int row = blockIdx.x;
    int tid = threadIdx.x;
    const float4 v = ((const float4*)(x + (size_t)row * CEMB))[tid];
    float s  = v.x + v.y + v.z + v.w;
    float sq = v.x * v.x + v.y * v.y + v.z * v.z + v.w * v.w;
    #pragma unroll
    for (int o = 16; o; o >>= 1) {
        s  += __shfl_xor_sync(0xffffffffu, s,  o);
        sq += __shfl_xor_sync(0xffffffffu, sq, o);
    }
    __shared__ float ss[8], sqs[8];
    if ((tid & 31) == 0) { ss[tid >> 5] = s; sqs[tid >> 5] = sq; }
    __syncthreads();
    float tot = 0.f, totq = 0.f;
    #pragma unroll
    for (int w = 0; w < 8; ++w) { tot += ss[w]; totq += sqs[w]; }
    const float mu   = tot * (1.f / CEMB);
    const float var  = totq * (1.f / CEMB) - mu * mu;
    const float rstd = rsqrtf(var + 1e-5f);
    const float4 gg = ((const float4*)g)[tid];
    const float4 bb = ((const float4*)b)[tid];
    size_t off = (size_t)row * CEMB + tid * 4;
    store_h2(oh, off,     (v.x - mu) * rstd * gg.x + bb.x, (v.y - mu) * rstd * gg.y + bb.y);
    store_h2(oh, off + 2, (v.z - mu) * rstd * gg.z + bb.z, (v.w - mu) * rstd * gg.w + bb.w);
}

// ---------------- weight transpose: w[K,N] f32 -> [N,K] fp16 ----------------
__global__ void wt_kernel(const float* __restrict__ w, __half* __restrict__ wh, int K, int N) {
    __shared__ float t[32][33];
    int n0 = blockIdx.x * 32, k0 = blockIdx.y * 32;
    int tx = threadIdx.x, ty = threadIdx.y;
    #pragma unroll
    for (int i = 0; i < 4; ++i)
        t[ty + 8 * i][tx] = w[(size_t)(k0 + ty + 8 * i) * N + n0 + tx];
    __syncthreads();
    #pragma unroll
    for (int i = 0; i < 4; ++i) {
        int r = ty + 8 * i;
        wh[(size_t)(n0 + r) * K + k0 + tx] = __float2half(t[tx][r]);
    }
}

__device__ __forceinline__ float gelu_t(float v) {
    float u = 0.7978845608028654f * (v + 0.044715f * v * v * v);
    return 0.5f * v * (1.f + tanhf(u));
}

// ---------------- HMMA GEMM 256x128, 8 warps (4m x 2n), warp tile 64x64 ----------------
// EPI: 1=bias+gelu->h, 2=bias+res->f32, 3=bias->h
#define TILE_M 256
#define TILE_N 128
#define KCH    64
#define STAGES 4
#define STG_BYTES (TILE_M * 128 + TILE_N * 128)   // 49152
#define GSMEM (STAGES * STG_BYTES)                // 196608

template<int EPI>
__global__ __launch_bounds__(256, 1) void hmma_gemm(
    const __half* __restrict__ A, const __half* __restrict__ B,
    const float* __restrict__ bias, const float* __restrict__ res,
    float* __restrict__ Cf, __half* __restrict__ Ch,
    int M, int N, int K)
{
    extern __shared__ char smem[];
    const uint32_t sb = s2u(smem);
    const int tid = threadIdx.x, wid = tid >> 5, lane = tid & 31;
    const int wm = wid & 3, wn = wid >> 2;                 // 4 x 2 warp grid
    const int row0 = blockIdx.y * TILE_M, col0 = blockIdx.x * TILE_N;
    const int NKC = K / KCH;

    auto load_chunk = [&](int kc) {
        int s = kc % STAGES;
        int k0 = kc * KCH;
        uint32_t sA = sb + s * STG_BYTES;
        uint32_t sB = sA + TILE_M * 128;
        #pragma unroll
        for (int i = 0; i < 8; ++i) {
            int idx = i * 256 + tid;
            int r = idx >> 3, c = (idx & 7) * 16;
            cp16(sA + swz(r * 128 + c), A + (size_t)(row0 + r) * K + k0 + (c >> 1));
        }
        #pragma unroll
        for (int i = 0; i < 4; ++i) {
            int idx = i * 256 + tid;
            int r = idx >> 3, c = (idx & 7) * 16;
            cp16(sB + swz(r * 128 + c), B + (size_t)(col0 + r) * K + k0 + (c >> 1));
        }
        cp_commit();
    };

    float acc[4][8][4];
    #pragma unroll
    for (int mt = 0; mt < 4; ++mt)
        #pragma unroll
        for (int nt = 0; nt < 8; ++nt)
            #pragma unroll
            for (int q = 0; q < 4; ++q) acc[mt][nt][q] = 0.f;

    for (int kc = 0; kc < STAGES - 1; ++kc) load_chunk(kc);

    const int arow = (lane & 7) + ((lane >> 3) & 1) * 8;
    const int akof = ((lane >> 4) & 1) * 8;
    const int nsel = (lane >> 4) & 1;
    const int bro  = lane & 7;
    const int bk8  = ((lane >> 3) & 1) * 8;

    for (int kc = 0; kc < NKC; ++kc) {
        int s = kc % STAGES;
        CP_WAIT(STAGES - 2);
        __syncthreads();
        if (kc + STAGES - 1 < NKC) load_chunk(kc + STAGES - 1);
        else cp_commit();
        uint32_t sA = sb + s * STG_BYTES;
        uint32_t sB = sA + TILE_M * 128;
        #pragma unroll
        for (int ks = 0; ks < KCH / 16; ++ks) {
            uint32_t a[4][4], b[8][2];
            #pragma unroll
            for (int mt = 0; mt < 4; ++mt) {
                uint32_t o = (uint32_t)(wm * 64 + mt * 16 + arow) * 128 + (ks * 16 + akof) * 2;
                ldsm4(a[mt], sA + swz(o));
            }
            #pragma unroll
            for (int ntp = 0; ntp < 4; ++ntp) {
                uint32_t o = (uint32_t)(wn * 64 + (2 * ntp + nsel) * 8 + bro) * 128 +
                             (ks * 16 + bk8) * 2;
                uint32_t r4[4];
                ldsm4(r4, sB + swz(o));
                b[2 * ntp][0] = r4[0]; b[2 * ntp][1] = r4[1];
                b[2 * ntp + 1][0] = r4[2]; b[2 * ntp + 1][1] = r4[3];
            }
            #pragma unroll
            for (int mt = 0; mt < 4; ++mt)
                #pragma unroll
                for (int nt = 0; nt < 8; ++nt)
                    mma16816(acc[mt][nt], a[mt], b[nt]);
        }
    }

    const int g = lane >> 2, i2 = (lane & 3) * 2;
    #pragma unroll
    for (int mt = 0; mt < 4; ++mt) {
        #pragma unroll
        for (int nt = 0; nt < 8; ++nt) {
            int r = row0 + wm * 64 + mt * 16 + g;
            int c = col0 + wn * 64 + nt * 8 + i2;
            float2 bv = *(const float2*)(bias + c);
            #pragma unroll
            for (int half = 0; half < 2; ++half) {
                int rr = r + half * 8;
                float v0 = acc[mt][nt][half * 2 + 0] + bv.x;
                float v1 = acc[mt][nt][half * 2 + 1] + bv.y;
                if (EPI == 1) {
                    store_h2(Ch, (size_t)rr * N + c, gelu_t(v0), gelu_t(v1));
                } else if (EPI == 3) {
                    store_h2(Ch, (size_t)rr * N + c, v0, v1);
                } else {
                    float2 rv = *(const float2*)(res + (size_t)rr * N + c);
                    float2 ov; ov.x = v0 + rv.x; ov.y = v1 + rv.y;
                    *(float2*)(Cf + (size_t)rr * N + c) = ov;
                }
            }
        }
    }
}

// ---------------- HMMA flash attention (fp16 single-pass) ----------------
// Q tile 128 (8 warps x 16 rows), K tile 64. smem: Q 16KB + 2 stages x 16KB = 48KB.
#define AQT 128
#define AKT 64
#define ASMEM (16384 + 2 * 16384)   // 49152

__global__ __launch_bounds__(256, 2) void attn_hmma(
    const __half* __restrict__ qkv, __half* __restrict__ y)
{
    extern __shared__ char smem[];
    const uint32_t sb = s2u(smem);
    const int tid = threadIdx.x, wid = tid >> 5, lane = tid & 31;
    const int qb = blockIdx.x, bh = blockIdx.y;
    const int b = bh >> 4, h = bh & 15;
    const int q0 = qb * AQT;
    const size_t rowbase = (size_t)b * SEQ;
    const size_t qcol = (size_t)h * HDIM, kcol = CEMB + qcol, vcol = 2 * CEMB + qcol;

    const uint32_t sQ = sb;

    // G0: Q tile (16KB)
    #pragma unroll
    for (int i = 0; i < 4; ++i) {
        int idx = i * 256 + tid;
        int r = idx >> 3, c = (idx & 7) * 16;
        cp16(sQ + swz(r * 128 + c), qkv + (rowbase + q0 + r) * C3 + qcol + (c >> 1));
    }
    cp_commit();

    auto load_kv = [&](int kt, int s) {
        uint32_t base = sb + 16384 + s * 16384;
        #pragma unroll
        for (int i = 0; i < 2; ++i) {
            int idx = i * 256 + tid;
            int r = idx >> 3, c = (idx & 7) * 16;
            size_t grow = (rowbase + kt * AKT + r) * C3;
            uint32_t so = swz(r * 128 + c);
            cp16(base + so,        qkv + grow + kcol + (c >> 1));
            cp16(base + 8192 + so, qkv + grow + vcol + (c >> 1));
        }
        cp_commit();
    };

    const int nkt = 2 * qb + 2;
    load_kv(0, 0);
    load_kv(1, 1);

    float m0 = -1e30f, m1 = -1e30f, l0 = 0.f, l1 = 0.f;
    float o_[8][4];
    #pragma unroll
    for (int nt = 0; nt < 8; ++nt)
        #pragma unroll
        for (int q = 0; q < 4; ++q) o_[nt][q] = 0.f;

    const int g = lane >> 2;
    const int qr0 = q0 + wid * 16 + g;
    const int ccol = (lane & 3) * 2;
    const int frow = (lane & 7) + ((lane >> 3) & 1) * 8;
    const int fkof = ((lane >> 4) & 1) * 8;
    const int nsel = (lane >> 4) & 1;
    const int bro  = lane & 7;
    const int bk8  = ((lane >> 3) & 1) * 8;
    const int vrow = lane & 15;
    const int vsel = (lane >> 4) & 1;

    for (int kt = 0; kt < nkt; ++kt) {
        int s = kt & 1;
        CP_WAIT(1);
        __syncthreads();
        uint32_t K_ = sb + 16384 + s * 16384;
        uint32_t V_ = K_ + 8192;

        // S = Q K^T
        float sa[8][4];
        #pragma unroll
        for (int nt = 0; nt < 8; ++nt)
            sa[nt][0] = sa[nt][1] = sa[nt][2] = sa[nt][3] = 0.f;
        #pragma unroll
        for (int ks = 0; ks < 4; ++ks) {
            uint32_t qo = (uint32_t)(wid * 16 + frow) * 128 + (ks * 16 + fkof) * 2;
            uint32_t q4[4];
            ldsm4(q4, sQ + swz(qo));
            #pragma unroll
            for (int ntp = 0; ntp < 4; ++ntp) {
                uint32_t ko = (uint32_t)((2 * ntp + nsel) * 8 + bro) * 128 + (ks * 16 + bk8) * 2;
                uint32_t k4[4];
                ldsm4(k4, K_ + swz(ko));
                mma16816(sa[2 * ntp],     q4, k4);
                mma16816(sa[2 * ntp + 1], q4, k4 + 2);
            }
        }

        // scale + causal mask
        const int k0g = kt * AKT;
        const bool tmask = (k0g + AKT - 1) > qr0;
        #pragma unroll
        for (int nt = 0; nt < 8; ++nt) {
            int c0g = k0g + nt * 8 + ccol;
            #pragma unroll
            for (int q = 0; q < 4; ++q) sa[nt][q] *= 0.125f;
            if (tmask) {
                if (c0g > qr0)         sa[nt][0] = -1e30f;
                if (c0g + 1 > qr0)     sa[nt][1] = -1e30f;
                if (c0g > qr0 + 8)     sa[nt][2] = -1e30f;
                if (c0g + 1 > qr0 + 8) sa[nt][3] = -1e30f;
            }
        }

        // online softmax
        float mt0 = -1e30f, mt1 = -1e30f;
        #pragma unroll
        for (int nt = 0; nt < 8; ++nt) {
            mt0 = fmaxf(mt0, fmaxf(sa[nt][0], sa[nt][1]));
            mt1 = fmaxf(mt1, fmaxf(sa[nt][2], sa[nt][3]));
        }
        mt0 = fmaxf(mt0, __shfl_xor_sync(0xffffffffu, mt0, 1));
        mt0 = fmaxf(mt0, __shfl_xor_sync(0xffffffffu, mt0, 2));
        mt1 = fmaxf(mt1, __shfl_xor_sync(0xffffffffu, mt1, 1));
        mt1 = fmaxf(mt1, __shfl_xor_sync(0xffffffffu, mt1, 2));
        float mn0 = fmaxf(m0, mt0), mn1 = fmaxf(m1, mt1);
        float a0 = __expf(m0 - mn0), a1 = __expf(m1 - mn1);
        m0 = mn0; m1 = mn1;
        float rs0 = 0.f, rs1 = 0.f;
        #pragma unroll
        for (int nt = 0; nt < 8; ++nt) {
            sa[nt][0] = __expf(sa[nt][0] - mn0);
            sa[nt][1] = __expf(sa[nt][1] - mn0);
            sa[nt][2] = __expf(sa[nt][2] - mn1);
            sa[nt][3] = __expf(sa[nt][3] - mn1);
            rs0 += sa[nt][0] + sa[nt][1];
            rs1 += sa[nt][2] + sa[nt][3];
        }
        rs0 += __shfl_xor_sync(0xffffffffu, rs0, 1);
        rs0 += __shfl_xor_sync(0xffffffffu, rs0, 2);
        rs1 += __shfl_xor_sync(0xffffffffu, rs1, 1);
        rs1 += __shfl_xor_sync(0xffffffffu, rs1, 2);
        l0 = l0 * a0 + rs0;
        l1 = l1 * a1 + rs1;
        #pragma unroll
        for (int nt = 0; nt < 8; ++nt) {
            o_[nt][0] *= a0; o_[nt][1] *= a0;
            o_[nt][2] *= a1; o_[nt][3] *= a1;
        }

        // pack P to fp16 A-fragments in registers
        uint32_t ph[4][4];
        #pragma unroll
        for (int ks = 0; ks < 4; ++ks) {
            ph[ks][0] = packh2(sa[2 * ks][0],     sa[2 * ks][1]);
            ph[ks][1] = packh2(sa[2 * ks][2],     sa[2 * ks][3]);
            ph[ks][2] = packh2(sa[2 * ks + 1][0], sa[2 * ks + 1][1]);
            ph[ks][3] = packh2(sa[2 * ks + 1][2], sa[2 * ks + 1][3]);
        }

        // O += P V, V via paired ldmatrix.x4.trans
        #pragma unroll
        for (int ks = 0; ks < 4; ++ks) {
            #pragma unroll
            for (int ntp = 0; ntp < 4; ++ntp) {
                uint32_t vo = (uint32_t)(ks * 16 + vrow) * 128 + (2 * ntp + vsel) * 16;
                uint32_t v4[4];
                ldsm4t(v4, V_ + swz(vo));
                mma16816(o_[2 * ntp],     ph[ks], v4);
                mma16816(o_[2 * ntp + 1], ph[ks], v4 + 2);
            }
        }
        __syncthreads();
        if (kt + 2 < nkt) load_kv(kt + 2, s);
        else cp_commit();
    }

    // epilogue: y = O / l -> fp16
    float i0 = 1.f / l0, i1 = 1.f / l1;
    #pragma unroll
    for (int nt = 0; nt < 8; ++nt) {
        size_t col = qcol + nt * 8 + ccol;
        store_h2(y, (rowbase + qr0) * CEMB + col,     o_[nt][0] * i0, o_[nt][1] * i0);
        store_h2(y, (rowbase + qr0 + 8) * CEMB + col, o_[nt][2] * i1, o_[nt][3] * i1);
    }
}

// ---------------- launch ----------------
extern "C" void kernel_launch(void* const* d_in, const int* in_sizes, int n_in,
                              void* d_out, int out_size) {
    const float* x      = (const float*)d_in[0];
    const float* ln1_g  = (const float*)d_in[1];
    const float* ln1_b  = (const float*)d_in[2];
    const float* w_attn = (const float*)d_in[3];
    const float* b_attn = (const float*)d_in[4];
    const float* w_proj = (const float*)d_in[5];
    const float* b_proj = (const float*)d_in[6];
    const float* ln2_g  = (const float*)d_in[7];
    const float* ln2_b  = (const float*)d_in[8];
    const float* w_fc   = (const float*)d_in[9];
    const float* b_fc   = (const float*)d_in[10];
    const float* w_fc2  = (const float*)d_in[11];
    const float* b_fc2  = (const float*)d_in[12];
    float* out = (float*)d_out;

    void* p;
    cudaGetSymbolAddress(&p, g_x2);  float* x2  = (float*)p;
    cudaGetSymbolAddress(&p, g_qkv); __half* qv = (__half*)p;
    cudaGetSymbolAddress(&p, g_a);   __half* ah = (__half*)p;
    cudaGetSymbolAddress(&p, g_y);   __half* yh = (__half*)p;
    cudaGetSymbolAddress(&p, g_h);   __half* hh = (__half*)p;
    cudaGetSymbolAddress(&p, g_wq);  __half* wq = (__half*)p;
    cudaGetSymbolAddress(&p, g_wp);  __half* wp = (__half*)p;
    cudaGetSymbolAddress(&p, g_wf);  __half* wf = (__half*)p;
    cudaGetSymbolAddress(&p, g_w2);  __half* w2 = (__half*)p;

    cudaFuncSetAttribute(hmma_gemm<1>, cudaFuncAttributeMaxDynamicSharedMemorySize, GSMEM);
    cudaFuncSetAttribute(hmma_gemm<2>, cudaFuncAttributeMaxDynamicSharedMemorySize, GSMEM);
    cudaFuncSetAttribute(hmma_gemm<3>, cudaFuncAttributeMaxDynamicSharedMemorySize, GSMEM);
    cudaFuncSetAttribute(attn_hmma, cudaFuncAttributeMaxDynamicSharedMemorySize, ASMEM);

    dim3 wtb(32, 8);
    wt_kernel<<<dim3(C3 / 32,  CEMB / 32), wtb>>>(w_attn, wq, CEMB, C3);
    wt_kernel<<<dim3(CEMB / 32, CEMB / 32), wtb>>>(w_proj, wp, CEMB, CEMB);
    wt_kernel<<<dim3(C4 / 32,  CEMB / 32), wtb>>>(w_fc,   wf, CEMB, C4);
    wt_kernel<<<dim3(CEMB / 32, C4 / 32),  wtb>>>(w_fc2,  w2, C4,   CEMB);

    // 1) ln1(x) -> fp16
    ln_h_kernel<<<ROWS, 256>>>(x, ln1_g, ln1_b, ah);
    // 2) qkv = ln1 @ w_attn + b_attn -> fp16
    hmma_gemm<3><<<dim3(C3 / TILE_N, ROWS / TILE_M), 256, GSMEM>>>(
        ah, wq, b_attn, nullptr, nullptr, qv, ROWS, C3, CEMB);
    // 3) attention -> fp16 y
    attn_hmma<<<dim3(SEQ / AQT, BATCH * NHEAD), 256, ASMEM>>>(qv, yh);
    // 4) x2 = x + y @ w_proj + b_proj (f32)
    hmma_gemm<2><<<dim3(CEMB / TILE_N, ROWS / TILE_M), 256, GSMEM>>>(
        yh, wp, b_proj, x, x2, nullptr, ROWS, CEMB, CEMB);
    // 5) ln2(x2) -> fp16
    ln_h_kernel<<<ROWS, 256>>>(x2, ln2_g, ln2_b, ah);
    // 6) h = gelu(ln2 @ w_fc + b_fc) -> fp16
    hmma_gemm<1><<<dim3(C4 / TILE_N, ROWS / TILE_M), 256, GSMEM>>>(
        ah, wf, b_fc, nullptr, nullptr, hh, ROWS, C4, CEMB);
    // 7) out = x2 + h @ w_fc2 + b_fc2 (f32)
    hmma_gemm<2><<<dim3(CEMB / TILE_N, ROWS / TILE_M), 256, GSMEM>>>(
        hh, w2, b_fc2, x2, out, nullptr, ROWS, CEMB, C4);
}

// round 15
// speedup vs baseline: 4.6444x; 1.0047x over previous
#include <cuda_runtime.h>
#include <cuda_bf16.h>
#include <cuda_fp16.h>
#include <math.h>
#include <stdint.h>

// ---------------- problem constants ----------------
#define BATCH 4
#define SEQ   2048
#define CEMB  1024
#define NHEAD 16
#define HDIM  64
#define ROWS  (BATCH*SEQ)        // 8192
#define C3    (3*CEMB)           // 3072
#define C4    (4*CEMB)           // 4096

// ---------------- scratch (no cudaMalloc allowed) ----------------
__device__ float  g_x2 [(size_t)ROWS*CEMB];
__device__ __half g_qkv[(size_t)ROWS*C3];
__device__ __half g_a  [(size_t)ROWS*CEMB];
__device__ __half g_y  [(size_t)ROWS*CEMB];
__device__ __half g_h  [(size_t)ROWS*C4];
__device__ __half g_wq [(size_t)C3*CEMB];
__device__ __half g_wp [(size_t)CEMB*CEMB];
__device__ __half g_wf [(size_t)C4*CEMB];
__device__ __half g_w2 [(size_t)CEMB*C4];

// ---------------- PTX helpers (family-safe: cp.async / ldmatrix / mma.sync) ----------------
__device__ __forceinline__ uint32_t s2u(const void* p) {
    uint32_t a;
    asm("{ .reg .u64 t; cvta.to.shared.u64 t, %1; cvt.u32.u64 %0, t; }" : "=r"(a) : "l"(p));
    return a;
}
__device__ __forceinline__ uint32_t swz(uint32_t o) { return o ^ ((o >> 3) & 0x70); }

__device__ __forceinline__ void cp16(uint32_t s, const void* g) {
    asm volatile("cp.async.cg.shared.global [%0], [%1], 16;" :: "r"(s), "l"(g));
}
__device__ __forceinline__ void cp_commit() { asm volatile("cp.async.commit_group;"); }
#define CP_WAIT(N) asm volatile("cp.async.wait_group %0;" :: "n"(N))

__device__ __forceinline__ void ldsm4(uint32_t* r, uint32_t addr) {
    asm volatile("ldmatrix.sync.aligned.m8n8.x4.shared.b16 {%0,%1,%2,%3}, [%4];"
                 : "=r"(r[0]), "=r"(r[1]), "=r"(r[2]), "=r"(r[3]) : "r"(addr));
}
__device__ __forceinline__ void ldsm4t(uint32_t* r, uint32_t addr) {
    asm volatile("ldmatrix.sync.aligned.m8n8.x4.trans.shared.b16 {%0,%1,%2,%3}, [%4];"
                 : "=r"(r[0]), "=r"(r[1]), "=r"(r[2]), "=r"(r[3]) : "r"(addr));
}
// fp16 inputs, fp32 accumulate
__device__ __forceinline__ void mma16816(float* c, const uint32_t* a, const uint32_t* b) {
    asm volatile("mma.sync.aligned.m16n8k16.row.col.f32.f16.f16.f32 "
                 "{%0,%1,%2,%3}, {%4,%5,%6,%7}, {%8,%9}, {%0,%1,%2,%3};"
                 : "+f"(c[0]), "+f"(c[1]), "+f"(c[2]), "+f"(c[3])
                 : "r"(a[0]), "r"(a[1]), "r"(a[2]), "r"(a[3]), "r"(b[0]), "r"(b[1]));
}

__device__ __forceinline__ uint32_t packh2(float x, float y) {
    __half2 h = __floats2half2_rn(x, y);
    return *reinterpret_cast<uint32_t*>(&h);
}
__device__ __forceinline__ void store_h2(__half* p, size_t off, float v0, float v1) {
    __half2 h = __floats2half2_rn(v0, v1);
    *reinterpret_cast<__half2*>(p + off) = h;
}

// ---------------- layernorm -> fp16 ----------------
__global__ void ln_h_kernel(const float* __restrict__ x, const float* __restrict__ g,
                            const float* __restrict__ b, __half* __restrict__ oh) {
    int row = blockIdx.x;
    int tid = threadIdx.x;
    const float4 v = ((const float4*)(x + (size_t)row * CEMB))[tid];
    float s  = v.x + v.y + v.z + v.w;
    float sq = v.x * v.x + v.y * v.y + v.z * v.z + v.w * v.w;
    #pragma unroll
    for (int o = 16; o; o >>= 1) {
        s  += __shfl_xor_sync(0xffffffffu, s,  o);
        sq += __shfl_xor_sync(0xffffffffu, sq, o);
    }
    __shared__ float ss[8], sqs[8];
    if ((tid & 31) == 0) { ss[tid >> 5] = s; sqs[tid >> 5] = sq; }
    __syncthreads();
    float tot = 0.f, totq = 0.f;
    #pragma unroll
    for (int w = 0; w < 8; ++w) { tot += ss[w]; totq += sqs[w]; }
    const float mu   = tot * (1.f / CEMB);
    const float var  = totq * (1.f / CEMB) - mu * mu;
    const float rstd = rsqrtf(var + 1e-5f);
    const float4 gg = ((const float4*)g)[tid];
    const float4 bb = ((const float4*)b)[tid];
    size_t off = (size_t)row * CEMB + tid * 4;
    store_h2(oh, off,     (v.x - mu) * rstd * gg.x + bb.x, (v.y - mu) * rstd * gg.y + bb.y);
    store_h2(oh, off + 2, (v.z - mu) * rstd * gg.z + bb.z, (v.w - mu) * rstd * gg.w + bb.w);
}

// ---------------- merged weight transpose: all 4 weights, one launch ----------------
// tiles: wq 3072 | wp 1024 | wf 4096 | w2 4096 -> 12288 blocks of (32,8)
__global__ void wt_all_kernel(const float* __restrict__ w_attn, __half* __restrict__ wq,
                              const float* __restrict__ w_proj, __half* __restrict__ wp,
                              const float* __restrict__ w_fc,   __half* __restrict__ wf,
                              const float* __restrict__ w_fc2,  __half* __restrict__ w2) {
    int id = blockIdx.x;
    const float* w; __half* wh; int K, N, nt, kt;
    if (id < 3072)      { w = w_attn; wh = wq; K = CEMB; N = C3;   nt = id % 96;  kt = id / 96;  }
    else if (id < 4096) { id -= 3072; w = w_proj; wh = wp; K = CEMB; N = CEMB; nt = id % 32;  kt = id / 32;  }
    else if (id < 8192) { id -= 4096; w = w_fc;   wh = wf; K = CEMB; N = C4;   nt = id % 128; kt = id / 128; }
    else                { id -= 8192; w = w_fc2;  wh = w2; K = C4;   N = CEMB; nt = id % 32;  kt = id / 32;  }
    const int n0 = nt * 32, k0 = kt * 32;

    __shared__ float t[32][33];
    int tx = threadIdx.x, ty = threadIdx.y;
    #pragma unroll
    for (int i = 0; i < 4; ++i)
        t[ty + 8 * i][tx] = w[(size_t)(k0 + ty + 8 * i) * N + n0 + tx];
    __syncthreads();
    #pragma unroll
    for (int i = 0; i < 4; ++i) {
        int r = ty + 8 * i;
        wh[(size_t)(n0 + r) * K + k0 + tx] = __float2half(t[tx][r]);
    }
}

__device__ __forceinline__ float gelu_t(float v) {
    float u = 0.7978845608028654f * (v + 0.044715f * v * v * v);
    return 0.5f * v * (1.f + tanhf(u));
}

// ---------------- HMMA GEMM 256x128, 8 warps (4m x 2n), warp tile 64x64 ----------------
// EPI: 1=bias+gelu->h, 2=bias+res->f32, 3=bias->h
#define TILE_M 256
#define TILE_N 128
#define KCH    64
#define STAGES 4
#define STG_BYTES (TILE_M * 128 + TILE_N * 128)   // 49152
#define GSMEM (STAGES * STG_BYTES)                // 196608

template<int EPI>
__global__ __launch_bounds__(256, 1) void hmma_gemm(
    const __half* __restrict__ A, const __half* __restrict__ B,
    const float* __restrict__ bias, const float* __restrict__ res,
    float* __restrict__ Cf, __half* __restrict__ Ch,
    int M, int N, int K)
{
    extern __shared__ char smem[];
    const uint32_t sb = s2u(smem);
    const int tid = threadIdx.x, wid = tid >> 5, lane = tid & 31;
    const int wm = wid & 3, wn = wid >> 2;                 // 4 x 2 warp grid
    const int row0 = blockIdx.y * TILE_M, col0 = blockIdx.x * TILE_N;
    const int NKC = K / KCH;

    auto load_chunk = [&](int kc) {
        int s = kc % STAGES;
        int k0 = kc * KCH;
        uint32_t sA = sb + s * STG_BYTES;
        uint32_t sB = sA + TILE_M * 128;
        #pragma unroll
        for (int i = 0; i < 8; ++i) {
            int idx = i * 256 + tid;
            int r = idx >> 3, c = (idx & 7) * 16;
            cp16(sA + swz(r * 128 + c), A + (size_t)(row0 + r) * K + k0 + (c >> 1));
        }
        #pragma unroll
        for (int i = 0; i < 4; ++i) {
            int idx = i * 256 + tid;
            int r = idx >> 3, c = (idx & 7) * 16;
            cp16(sB + swz(r * 128 + c), B + (size_t)(col0 + r) * K + k0 + (c >> 1));
        }
        cp_commit();
    };

    float acc[4][8][4];
    #pragma unroll
    for (int mt = 0; mt < 4; ++mt)
        #pragma unroll
        for (int nt = 0; nt < 8; ++nt)
            #pragma unroll
            for (int q = 0; q < 4; ++q) acc[mt][nt][q] = 0.f;

    for (int kc = 0; kc < STAGES - 1; ++kc) load_chunk(kc);

    const int arow = (lane & 7) + ((lane >> 3) & 1) * 8;
    const int akof = ((lane >> 4) & 1) * 8;
    const int nsel = (lane >> 4) & 1;
    const int bro  = lane & 7;
    const int bk8  = ((lane >> 3) & 1) * 8;

    for (int kc = 0; kc < NKC; ++kc) {
        int s = kc % STAGES;
        CP_WAIT(STAGES - 2);
        __syncthreads();
        if (kc + STAGES - 1 < NKC) load_chunk(kc + STAGES - 1);
        else cp_commit();
        uint32_t sA = sb + s * STG_BYTES;
        uint32_t sB = sA + TILE_M * 128;
        #pragma unroll
        for (int ks = 0; ks < KCH / 16; ++ks) {
            uint32_t a[4][4], b[8][2];
            #pragma unroll
            for (int mt = 0; mt < 4; ++mt) {
                uint32_t o = (uint32_t)(wm * 64 + mt * 16 + arow) * 128 + (ks * 16 + akof) * 2;
                ldsm4(a[mt], sA + swz(o));
            }
            #pragma unroll
            for (int ntp = 0; ntp < 4; ++ntp) {
                uint32_t o = (uint32_t)(wn * 64 + (2 * ntp + nsel) * 8 + bro) * 128 +
                             (ks * 16 + bk8) * 2;
                uint32_t r4[4];
                ldsm4(r4, sB + swz(o));
                b[2 * ntp][0] = r4[0]; b[2 * ntp][1] = r4[1];
                b[2 * ntp + 1][0] = r4[2]; b[2 * ntp + 1][1] = r4[3];
            }
            #pragma unroll
            for (int mt = 0; mt < 4; ++mt)
                #pragma unroll
                for (int nt = 0; nt < 8; ++nt)
                    mma16816(acc[mt][nt], a[mt], b[nt]);
        }
    }

    const int g = lane >> 2, i2 = (lane & 3) * 2;
    #pragma unroll
    for (int mt = 0; mt < 4; ++mt) {
        #pragma unroll
        for (int nt = 0; nt < 8; ++nt) {
            int r = row0 + wm * 64 + mt * 16 + g;
            int c = col0 + wn * 64 + nt * 8 + i2;
            float2 bv = *(const float2*)(bias + c);
            #pragma unroll
            for (int half = 0; half < 2; ++half) {
                int rr = r + half * 8;
                float v0 = acc[mt][nt][half * 2 + 0] + bv.x;
                float v1 = acc[mt][nt][half * 2 + 1] + bv.y;
                if (EPI == 1) {
                    store_h2(Ch, (size_t)rr * N + c, gelu_t(v0), gelu_t(v1));
                } else if (EPI == 3) {
                    store_h2(Ch, (size_t)rr * N + c, v0, v1);
                } else {
                    float2 rv = *(const float2*)(res + (size_t)rr * N + c);
                    float2 ov; ov.x = v0 + rv.x; ov.y = v1 + rv.y;
                    *(float2*)(Cf + (size_t)rr * N + c) = ov;
                }
            }
        }
    }
}

// ---------------- HMMA flash attention (fp16 single-pass) ----------------
// Q tile 128 (8 warps x 16 rows), K tile 64. smem: Q 16KB + 2 stages x 16KB = 48KB.
// Heavy tiles (large qb) issued FIRST for better wave packing.
#define AQT 128
#define AKT 64
#define ASMEM (16384 + 2 * 16384)   // 49152

__global__ __launch_bounds__(256, 2) void attn_hmma(
    const __half* __restrict__ qkv, __half* __restrict__ y)
{
    extern __shared__ char smem[];
    const uint32_t sb = s2u(smem);
    const int tid = threadIdx.x, wid = tid >> 5, lane = tid & 31;
    const int qb = gridDim.x - 1 - blockIdx.x;          // heavy-first ordering
    const int bh = blockIdx.y;
    const int b = bh >> 4, h = bh & 15;
    const int q0 = qb * AQT;
    const size_t rowbase = (size_t)b * SEQ;
    const size_t qcol = (size_t)h * HDIM, kcol = CEMB + qcol, vcol = 2 * CEMB + qcol;

    const uint32_t sQ = sb;

    // G0: Q tile (16KB)
    #pragma unroll
    for (int i = 0; i < 4; ++i) {
        int idx = i * 256 + tid;
        int r = idx >> 3, c = (idx & 7) * 16;
        cp16(sQ + swz(r * 128 + c), qkv + (rowbase + q0 + r) * C3 + qcol + (c >> 1));
    }
    cp_commit();

    auto load_kv = [&](int kt, int s) {
        uint32_t base = sb + 16384 + s * 16384;
        #pragma unroll
        for (int i = 0; i < 2; ++i) {
            int idx = i * 256 + tid;
            int r = idx >> 3, c = (idx & 7) * 16;
            size_t grow = (rowbase + kt * AKT + r) * C3;
            uint32_t so = swz(r * 128 + c);
            cp16(base + so,        qkv + grow + kcol + (c >> 1));
            cp16(base + 8192 + so, qkv + grow + vcol + (c >> 1));
        }
        cp_commit();
    };

    const int nkt = 2 * qb + 2;
    load_kv(0, 0);
    load_kv(1, 1);

    float m0 = -1e30f, m1 = -1e30f, l0 = 0.f, l1 = 0.f;
    float o_[8][4];
    #pragma unroll
    for (int nt = 0; nt < 8; ++nt)
        #pragma unroll
        for (int q = 0; q < 4; ++q) o_[nt][q] = 0.f;

    const int g = lane >> 2;
    const int qr0 = q0 + wid * 16 + g;
    const int ccol = (lane & 3) * 2;
    const int frow = (lane & 7) + ((lane >> 3) & 1) * 8;
    const int fkof = ((lane >> 4) & 1) * 8;
    const int nsel = (lane >> 4) & 1;
    const int bro  = lane & 7;
    const int bk8  = ((lane >> 3) & 1) * 8;
    const int vrow = lane & 15;
    const int vsel = (lane >> 4) & 1;

    for (int kt = 0; kt < nkt; ++kt) {
        int s = kt & 1;
        CP_WAIT(1);
        __syncthreads();
        uint32_t K_ = sb + 16384 + s * 16384;
        uint32_t V_ = K_ + 8192;

        // S = Q K^T
        float sa[8][4];
        #pragma unroll
        for (int nt = 0; nt < 8; ++nt)
            sa[nt][0] = sa[nt][1] = sa[nt][2] = sa[nt][3] = 0.f;
        #pragma unroll
        for (int ks = 0; ks < 4; ++ks) {
            uint32_t qo = (uint32_t)(wid * 16 + frow) * 128 + (ks * 16 + fkof) * 2;
            uint32_t q4[4];
            ldsm4(q4, sQ + swz(qo));
            #pragma unroll
            for (int ntp = 0; ntp < 4; ++ntp) {
                uint32_t ko = (uint32_t)((2 * ntp + nsel) * 8 + bro) * 128 + (ks * 16 + bk8) * 2;
                uint32_t k4[4];
                ldsm4(k4, K_ + swz(ko));
                mma16816(sa[2 * ntp],     q4, k4);
                mma16816(sa[2 * ntp + 1], q4, k4 + 2);
            }
        }

        // scale + causal mask
        const int k0g = kt * AKT;
        const bool tmask = (k0g + AKT - 1) > qr0;
        #pragma unroll
        for (int nt = 0; nt < 8; ++nt) {
            int c0g = k0g + nt * 8 + ccol;
            #pragma unroll
            for (int q = 0; q < 4; ++q) sa[nt][q] *= 0.125f;
            if (tmask) {
                if (c0g > qr0)         sa[nt][0] = -1e30f;
                if (c0g + 1 > qr0)     sa[nt][1] = -1e30f;
                if (c0g > qr0 + 8)     sa[nt][2] = -1e30f;
                if (c0g + 1 > qr0 + 8) sa[nt][3] = -1e30f;
            }
        }

        // online softmax
        float mt0 = -1e30f, mt1 = -1e30f;
        #pragma unroll
        for (int nt = 0; nt < 8; ++nt) {
            mt0 = fmaxf(mt0, fmaxf(sa[nt][0], sa[nt][1]));
            mt1 = fmaxf(mt1, fmaxf(sa[nt][2], sa[nt][3]));
        }
        mt0 = fmaxf(mt0, __shfl_xor_sync(0xffffffffu, mt0, 1));
        mt0 = fmaxf(mt0, __shfl_xor_sync(0xffffffffu, mt0, 2));
        mt1 = fmaxf(mt1, __shfl_xor_sync(0xffffffffu, mt1, 1));
        mt1 = fmaxf(mt1, __shfl_xor_sync(0xffffffffu, mt1, 2));
        float mn0 = fmaxf(m0, mt0), mn1 = fmaxf(m1, mt1);
        float a0 = __expf(m0 - mn0), a1 = __expf(m1 - mn1);
        m0 = mn0; m1 = mn1;
        float rs0 = 0.f, rs1 = 0.f;
        #pragma unroll
        for (int nt = 0; nt < 8; ++nt) {
            sa[nt][0] = __expf(sa[nt][0] - mn0);
            sa[nt][1] = __expf(sa[nt][1] - mn0);
            sa[nt][2] = __expf(sa[nt][2] - mn1);
            sa[nt][3] = __expf(sa[nt][3] - mn1);
            rs0 += sa[nt][0] + sa[nt][1];
            rs1 += sa[nt][2] + sa[nt][3];
        }
        rs0 += __shfl_xor_sync(0xffffffffu, rs0, 1);
        rs0 += __shfl_xor_sync(0xffffffffu, rs0, 2);
        rs1 += __shfl_xor_sync(0xffffffffu, rs1, 1);
        rs1 += __shfl_xor_sync(0xffffffffu, rs1, 2);
        l0 = l0 * a0 + rs0;
        l1 = l1 * a1 + rs1;
        #pragma unroll
        for (int nt = 0; nt < 8; ++nt) {
            o_[nt][0] *= a0; o_[nt][1] *= a0;
            o_[nt][2] *= a1; o_[nt][3] *= a1;
        }

        // pack P to fp16 A-fragments in registers
        uint32_t ph[4][4];
        #pragma unroll
        for (int ks = 0; ks < 4; ++ks) {
            ph[ks][0] = packh2(sa[2 * ks][0],     sa[2 * ks][1]);
            ph[ks][1] = packh2(sa[2 * ks][2],     sa[2 * ks][3]);
            ph[ks][2] = packh2(sa[2 * ks + 1][0], sa[2 * ks + 1][1]);
            ph[ks][3] = packh2(sa[2 * ks + 1][2], sa[2 * ks + 1][3]);
        }

        // O += P V, V via paired ldmatrix.x4.trans
        #pragma unroll
        for (int ks = 0; ks < 4; ++ks) {
            #pragma unroll
            for (int ntp = 0; ntp < 4; ++ntp) {
                uint32_t vo = (uint32_t)(ks * 16 + vrow) * 128 + (2 * ntp + vsel) * 16;
                uint32_t v4[4];
                ldsm4t(v4, V_ + swz(vo));
                mma16816(o_[2 * ntp],     ph[ks], v4);
                mma16816(o_[2 * ntp + 1], ph[ks], v4 + 2);
            }
        }
        __syncthreads();
        if (kt + 2 < nkt) load_kv(kt + 2, s);
        else cp_commit();
    }

    // epilogue: y = O / l -> fp16
    float i0 = 1.f / l0, i1 = 1.f / l1;
    #pragma unroll
    for (int nt = 0; nt < 8; ++nt) {
        size_t col = qcol + nt * 8 + ccol;
        store_h2(y, (rowbase + qr0) * CEMB + col,     o_[nt][0] * i0, o_[nt][1] * i0);
        store_h2(y, (rowbase + qr0 + 8) * CEMB + col, o_[nt][2] * i1, o_[nt][3] * i1);
    }
}

// ---------------- launch ----------------
extern "C" void kernel_launch(void* const* d_in, const int* in_sizes, int n_in,
                              void* d_out, int out_size) {
    const float* x      = (const float*)d_in[0];
    const float* ln1_g  = (const float*)d_in[1];
    const float* ln1_b  = (const float*)d_in[2];
    const float* w_attn = (const float*)d_in[3];
    const float* b_attn = (const float*)d_in[4];
    const float* w_proj = (const float*)d_in[5];
    const float* b_proj = (const float*)d_in[6];
    const float* ln2_g  = (const float*)d_in[7];
    const float* ln2_b  = (const float*)d_in[8];
    const float* w_fc   = (const float*)d_in[9];
    const float* b_fc   = (const float*)d_in[10];
    const float* w_fc2  = (const float*)d_in[11];
    const float* b_fc2  = (const float*)d_in[12];
    float* out = (float*)d_out;

    void* p;
    cudaGetSymbolAddress(&p, g_x2);  float* x2  = (float*)p;
    cudaGetSymbolAddress(&p, g_qkv); __half* qv = (__half*)p;
    cudaGetSymbolAddress(&p, g_a);   __half* ah = (__half*)p;
    cudaGetSymbolAddress(&p, g_y);   __half* yh = (__half*)p;
    cudaGetSymbolAddress(&p, g_h);   __half* hh = (__half*)p;
    cudaGetSymbolAddress(&p, g_wq);  __half* wq = (__half*)p;
    cudaGetSymbolAddress(&p, g_wp);  __half* wp = (__half*)p;
    cudaGetSymbolAddress(&p, g_wf);  __half* wf = (__half*)p;
    cudaGetSymbolAddress(&p, g_w2);  __half* w2 = (__half*)p;

    cudaFuncSetAttribute(hmma_gemm<1>, cudaFuncAttributeMaxDynamicSharedMemorySize, GSMEM);
    cudaFuncSetAttribute(hmma_gemm<2>, cudaFuncAttributeMaxDynamicSharedMemorySize, GSMEM);
    cudaFuncSetAttribute(hmma_gemm<3>, cudaFuncAttributeMaxDynamicSharedMemorySize, GSMEM);
    cudaFuncSetAttribute(attn_hmma, cudaFuncAttributeMaxDynamicSharedMemorySize, ASMEM);

    // all 4 weight transposes in ONE launch (12288 tiles)
    wt_all_kernel<<<12288, dim3(32, 8)>>>(w_attn, wq, w_proj, wp, w_fc, wf, w_fc2, w2);

    // 1) ln1(x) -> fp16
    ln_h_kernel<<<ROWS, 256>>>(x, ln1_g, ln1_b, ah);
    // 2) qkv = ln1 @ w_attn + b_attn -> fp16
    hmma_gemm<3><<<dim3(C3 / TILE_N, ROWS / TILE_M), 256, GSMEM>>>(
        ah, wq, b_attn, nullptr, nullptr, qv, ROWS, C3, CEMB);
    // 3) attention -> fp16 y (heavy q-tiles first)
    attn_hmma<<<dim3(SEQ / AQT, BATCH * NHEAD), 256, ASMEM>>>(qv, yh);
    // 4) x2 = x + y @ w_proj + b_proj (f32)
    hmma_gemm<2><<<dim3(CEMB / TILE_N, ROWS / TILE_M), 256, GSMEM>>>(
        yh, wp, b_proj, x, x2, nullptr, ROWS, CEMB, CEMB);
    // 5) ln2(x2) -> fp16
    ln_h_kernel<<<ROWS, 256>>>(x2, ln2_g, ln2_b, ah);
    // 6) h = gelu(ln2 @ w_fc + b_fc) -> fp16
    hmma_gemm<1><<<dim3(C4 / TILE_N, ROWS / TILE_M), 256, GSMEM>>>(
        ah, wf, b_fc, nullptr, nullptr, hh, ROWS, C4, CEMB);
    // 7) out = x2 + h @ w_fc2 + b_fc2 (f32)
    hmma_gemm<2><<<dim3(CEMB / TILE_N, ROWS / TILE_M), 256, GSMEM>>>(
        hh, w2, b_fc2, x2, out, nullptr, ROWS, CEMB, C4);
}